// round 3
// baseline (speedup 1.0000x reference)
#include <cuda_runtime.h>
#include <cuda_bf16.h>
#include <cstdint>
#include <math.h>

#define B_ 8
#define C_ 128
#define N_ 32768
#define NEL 4194304
#define MLP_ 512
#define EPS_ 1e-5f
#define SCALE_ 0.25f
#define LDE 136
#define LDW2 520
#define LDH 72
#define GLD 72

// ---------------- scratch (device globals; no runtime allocation) ----------
__device__ float         g_G[B_][C_][C_];
__device__ __nv_bfloat16 g_E[B_][C_][C_];
__device__ float         g_stats[4][B_];   // sum1,sq1,sum2,sq2 per batch
__device__ float         g_norm[4][B_];    // mu1,rs1,mu2,rs2
__device__ __nv_bfloat16 g_W1[MLP_*C_];
__device__ __nv_bfloat16 g_W2[C_*MLP_];
__device__ float         g_y [(size_t)B_*NEL];   // y, later reused as z
__device__ float         g_x1[(size_t)B_*NEL];
__device__ __nv_bfloat16 g_hid[(size_t)B_*MLP_*N_];

// ---------------- helpers ----------------
__device__ __forceinline__ uint32_t s2u(const void* p){
    return (uint32_t)__cvta_generic_to_shared(p);
}
__device__ __forceinline__ void ldsmx4(uint32_t* r, uint32_t a){
    asm volatile("ldmatrix.sync.aligned.m8n8.x4.shared.b16 {%0,%1,%2,%3},[%4];"
        : "=r"(r[0]),"=r"(r[1]),"=r"(r[2]),"=r"(r[3]) : "r"(a));
}
__device__ __forceinline__ void ldsmx4t(uint32_t* r, uint32_t a){
    asm volatile("ldmatrix.sync.aligned.m8n8.x4.trans.shared.b16 {%0,%1,%2,%3},[%4];"
        : "=r"(r[0]),"=r"(r[1]),"=r"(r[2]),"=r"(r[3]) : "r"(a));
}
__device__ __forceinline__ void mma_bf16(float* c, const uint32_t* a, const uint32_t* b){
    asm volatile("mma.sync.aligned.m16n8k16.row.col.f32.bf16.bf16.f32 "
        "{%0,%1,%2,%3},{%4,%5,%6,%7},{%8,%9},{%0,%1,%2,%3};"
        : "+f"(c[0]),"+f"(c[1]),"+f"(c[2]),"+f"(c[3])
        : "r"(a[0]),"r"(a[1]),"r"(a[2]),"r"(a[3]),"r"(b[0]),"r"(b[1]));
}
__device__ __forceinline__ float gelu_f(float v){
    return 0.5f*v*(1.0f+erff(v*0.70710678118654752f));
}

// ---------------- K0: zero scratch, convert MLP weights to bf16 ------------
__global__ void k_init(const float* __restrict__ w1, const float* __restrict__ w2){
    int i  = blockIdx.x*blockDim.x + threadIdx.x;
    int st = gridDim.x*blockDim.x;
    float* gg = &g_G[0][0][0];
    for(int t=i; t<B_*C_*C_; t+=st) gg[t] = 0.f;
    float* gs = &g_stats[0][0];
    for(int t=i; t<4*B_; t+=st) gs[t] = 0.f;
    for(int t=i; t<MLP_*C_; t+=st) g_W1[t] = __float2bfloat16(w1[t]);
    for(int t=i; t<C_*MLP_; t+=st) g_W2[t] = __float2bfloat16(w2[t]);
}

// ---------------- K1: per-batch Gram matrix G = X X^T ----------------------
// grid (64 splits, 8 batch); each CTA handles K-range of 512 spatial cols
__global__ void __launch_bounds__(256) k_gram(const float* __restrict__ x){
    __shared__ __nv_bfloat16 Xs[C_][GLD];
    int b = blockIdx.y, split = blockIdx.x;
    const float* xb = x + (size_t)b*NEL + split*512;
    int tid = threadIdx.x, lane = tid&31, warp = tid>>5;
    float acc[16][4];
    #pragma unroll
    for(int i=0;i<16;++i){ acc[i][0]=acc[i][1]=acc[i][2]=acc[i][3]=0.f; }
    for(int kc=0; kc<8; ++kc){
        const float* src = xb + kc*64;
        for(int idx=tid; idx<2048; idx+=256){   // 128 rows x 16 float4
            int row = idx>>4, c4 = idx&15;
            float4 v = *(const float4*)(src + (size_t)row*N_ + c4*4);
            __nv_bfloat162* d = (__nv_bfloat162*)&Xs[row][c4*4];
            d[0] = __floats2bfloat162_rn(v.x, v.y);
            d[1] = __floats2bfloat162_rn(v.z, v.w);
        }
        __syncthreads();
        int m0 = warp*16;
        #pragma unroll
        for(int ks=0; ks<4; ++ks){
            int k = ks*16;
            uint32_t a[4];
            ldsmx4(a, s2u(&Xs[m0 + (lane&15)][k + ((lane>>4)&1)*8]));
            #pragma unroll
            for(int nt=0; nt<8; ++nt){
                uint32_t Bv[4];
                ldsmx4(Bv, s2u(&Xs[nt*16 + (lane&7) + ((lane>>4)&1)*8][k + ((lane>>3)&1)*8]));
                mma_bf16(acc[nt*2+0], a, Bv);
                mma_bf16(acc[nt*2+1], a, Bv+2);
            }
        }
        __syncthreads();
    }
    float* Gb = &g_G[b][0][0];
    int r0 = warp*16 + (lane>>2);
    #pragma unroll
    for(int nt=0; nt<16; ++nt){
        int c0 = nt*8 + (lane&3)*2;
        atomicAdd(&Gb[(size_t)r0*C_ + c0],       acc[nt][0]);
        atomicAdd(&Gb[(size_t)r0*C_ + c0+1],     acc[nt][1]);
        atomicAdd(&Gb[(size_t)(r0+8)*C_ + c0],   acc[nt][2]);
        atomicAdd(&Gb[(size_t)(r0+8)*C_ + c0+1], acc[nt][3]);
    }
}

// ---------------- K2: attention epilogue -> per-batch E matrix -------------
// 8 CTAs (one per batch), 512 threads, fp32 math
__global__ void __launch_bounds__(512) k_attn(const float* __restrict__ qkv_w,
                                              const float* __restrict__ proj_w){
    extern __shared__ float sm2[];
    float* sG = sm2;            // 16384 : G, later M
    float* sT = sm2 + 16384;    // 16384 : T1 = Wq*G
    float* sA = sm2 + 32768;    // 2048  : attn
    int b = blockIdx.x, tid = threadIdx.x;
    const float* Gb = &g_G[b][0][0];
    for(int i=tid; i<16384; i+=512) sG[i] = Gb[i];
    __syncthreads();
    {   // T1[i][t] = sum_k Wq[i][k] * G[k][t]
        int t0 = tid & 127, g = tid >> 7;
        for(int ii=0; ii<32; ++ii){
            int i = g*32 + ii;
            const float* wq = qkv_w + (size_t)i*C_;
            float a = 0.f;
            #pragma unroll 8
            for(int k=0;k<C_;++k) a += wq[k]*sG[k*C_ + t0];
            sT[i*C_ + t0] = a;
        }
    }
    __syncthreads();
    if(tid < 128){   // logits + softmax, one row per thread
        int h = tid >> 4;
        float l[16], mx = -1e30f;
        for(int j=0;j<16;++j){
            const float* wk = qkv_w + (size_t)(C_ + h*16 + j)*C_;
            float a = 0.f;
            #pragma unroll 8
            for(int t=0;t<C_;++t) a += sT[tid*C_ + t]*wk[t];
            l[j] = a*SCALE_; mx = fmaxf(mx, l[j]);
        }
        float s = 0.f;
        for(int j=0;j<16;++j){ l[j] = expf(l[j]-mx); s += l[j]; }
        float inv = 1.f/s;
        for(int j=0;j<16;++j) sA[tid*16 + j] = l[j]*inv;
    }
    __syncthreads();
    // M[r][k] = sum_j A[r][j] * Wv[h*16+j][k]   (write over sG)
    for(int idx=tid; idx<16384; idx+=512){
        int r = idx>>7, k = idx&127, h = r>>4;
        float a = 0.f;
        #pragma unroll
        for(int j=0;j<16;++j)
            a += sA[r*16+j]*qkv_w[(size_t)(2*C_ + h*16 + j)*C_ + k];
        sG[r*C_ + k] = a;
    }
    __syncthreads();
    // E[o][k] = sum_r Wp[o][r] * M[r][k]  -> bf16 to gmem
    for(int idx=tid; idx<16384; idx+=512){
        int o = idx>>7, k = idx&127;
        const float* wp = proj_w + (size_t)o*C_;
        float a = 0.f;
        #pragma unroll 8
        for(int r=0;r<C_;++r) a += wp[r]*sG[r*C_ + k];
        g_E[b][o][k] = __float2bfloat16(a);
    }
}

// ---------------- K3: y = x + E*x + proj_b, LN1 stats ----------------------
// grid (256 n-tiles of 128, 8 batch), 256 thr
__global__ void __launch_bounds__(256) k_apply(const float* __restrict__ x,
                                               const float* __restrict__ proj_b){
    extern __shared__ __nv_bfloat16 sm3[];
    __nv_bfloat16* Es = sm3;              // [128][LDE]
    __nv_bfloat16* Xs = sm3 + C_*LDE;     // [128][LDE]
    int b = blockIdx.y, n0 = blockIdx.x*128;
    int tid = threadIdx.x, lane = tid&31, warp = tid>>5;
    const float* xb = x + (size_t)b*NEL + n0;
    for(int idx=tid; idx<2048; idx+=256){   // E: 128x128 bf16
        int r = idx>>4, c8 = (idx&15)*8;
        *(uint4*)&Es[r*LDE + c8] = *(const uint4*)&g_E[b][r][c8];
    }
    for(int idx=tid; idx<4096; idx+=256){   // x tile -> bf16 smem
        int r = idx>>5, c4 = (idx&31)*4;
        float4 v = *(const float4*)(xb + (size_t)r*N_ + c4);
        __nv_bfloat162* d = (__nv_bfloat162*)&Xs[r*LDE + c4];
        d[0] = __floats2bfloat162_rn(v.x, v.y);
        d[1] = __floats2bfloat162_rn(v.z, v.w);
    }
    __syncthreads();
    int m0 = warp*16;
    uint32_t A8[8][4];
    #pragma unroll
    for(int ks=0; ks<8; ++ks)
        ldsmx4(A8[ks], s2u(&Es[(m0 + (lane&15))*LDE + ks*16 + ((lane>>4)&1)*8]));
    float* yb = g_y + (size_t)b*NEL + n0;
    int r0 = m0 + (lane>>2);
    float pb0 = proj_b[r0], pb1 = proj_b[r0+8];
    float ls = 0.f, lq = 0.f;
    for(int ns=0; ns<8; ++ns){
        int n = ns*16;
        float acc[2][4] = {};
        #pragma unroll
        for(int ks=0; ks<8; ++ks){
            uint32_t Bv[4];
            ldsmx4t(Bv, s2u(&Xs[(ks*16 + (lane&7) + ((lane>>3)&1)*8)*LDE + n + ((lane>>4)&1)*8]));
            mma_bf16(acc[0], A8[ks], Bv);
            mma_bf16(acc[1], A8[ks], Bv+2);
        }
        #pragma unroll
        for(int nh=0; nh<2; ++nh){
            int cc = n + nh*8 + (lane&3)*2;
            float2 x0  = *(const float2*)(xb + (size_t)r0*N_ + cc);
            float2 x1v = *(const float2*)(xb + (size_t)(r0+8)*N_ + cc);
            float y00 = x0.x  + acc[nh][0] + pb0;
            float y01 = x0.y  + acc[nh][1] + pb0;
            float y10 = x1v.x + acc[nh][2] + pb1;
            float y11 = x1v.y + acc[nh][3] + pb1;
            *(float2*)(yb + (size_t)r0*N_ + cc)     = make_float2(y00, y01);
            *(float2*)(yb + (size_t)(r0+8)*N_ + cc) = make_float2(y10, y11);
            ls += y00+y01+y10+y11;
            lq += y00*y00 + y01*y01 + y10*y10 + y11*y11;
        }
    }
    #pragma unroll
    for(int o=16;o>0;o>>=1){ ls += __shfl_xor_sync(0xffffffffu, ls, o);
                             lq += __shfl_xor_sync(0xffffffffu, lq, o); }
    if(lane==0){ atomicAdd(&g_stats[0][b], ls); atomicAdd(&g_stats[1][b], lq); }
}

// ---------------- K4/K7: finalize LN stats ---------------------------------
__global__ void k_norm(int stage){
    int b = threadIdx.x;
    if(b < B_){
        float s = g_stats[stage*2][b], q = g_stats[stage*2+1][b];
        float mu = s / (float)NEL;
        float var = q / (float)NEL - mu*mu;
        g_norm[stage*2][b]   = mu;
        g_norm[stage*2+1][b] = rsqrtf(var + EPS_);
    }
}

// ---------------- K5: x1 = LN1(y), hid = gelu(W1 x1 + b1) ------------------
// grid (256, 8), 512 thr
__global__ void __launch_bounds__(512) k_mlp1(const float* __restrict__ ln1w,
                                              const float* __restrict__ ln1b,
                                              const float* __restrict__ b1){
    extern __shared__ __nv_bfloat16 sm5[];
    __nv_bfloat16* Ws = sm5;               // [512][LDE]
    __nv_bfloat16* Xs = sm5 + MLP_*LDE;    // [128][LDE]
    int b = blockIdx.y, n0 = blockIdx.x*128;
    int tid = threadIdx.x, lane = tid&31, warp = tid>>5;
    float mu = g_norm[0][b], rs = g_norm[1][b];
    for(int idx=tid; idx<8192; idx+=512){   // W1 512x128 bf16
        int r = idx>>4, c8 = (idx&15)*8;
        *(uint4*)&Ws[r*LDE + c8] = *(const uint4*)&g_W1[r*C_ + c8];
    }
    const float* yb  = g_y  + (size_t)b*NEL + n0;
    const float* wvp = ln1w + n0;
    const float* bvp = ln1b + n0;
    float* x1b = g_x1 + (size_t)b*NEL + n0;
    for(int idx=tid; idx<4096; idx+=512){
        int r = idx>>5, c4 = (idx&31)*4;
        size_t off = (size_t)r*N_ + c4;
        float4 y4 = *(const float4*)(yb + off);
        float4 w4 = *(const float4*)(wvp + off);
        float4 b4 = *(const float4*)(bvp + off);
        float4 o;
        o.x = (y4.x-mu)*rs*w4.x + b4.x;
        o.y = (y4.y-mu)*rs*w4.y + b4.y;
        o.z = (y4.z-mu)*rs*w4.z + b4.z;
        o.w = (y4.w-mu)*rs*w4.w + b4.w;
        *(float4*)(x1b + off) = o;
        __nv_bfloat162* d = (__nv_bfloat162*)&Xs[r*LDE + c4];
        d[0] = __floats2bfloat162_rn(o.x, o.y);
        d[1] = __floats2bfloat162_rn(o.z, o.w);
    }
    __syncthreads();
    int m0 = warp*32;
    __nv_bfloat16* hidb = g_hid + (size_t)b*MLP_*N_ + n0;
    for(int ns=0; ns<8; ++ns){
        int n = ns*16;
        float acc[2][2][4] = {};
        #pragma unroll
        for(int ks=0; ks<8; ++ks){
            uint32_t Bv[4];
            ldsmx4t(Bv, s2u(&Xs[(ks*16 + (lane&7) + ((lane>>3)&1)*8)*LDE + n + ((lane>>4)&1)*8]));
            #pragma unroll
            for(int mt=0; mt<2; ++mt){
                uint32_t Av[4];
                ldsmx4(Av, s2u(&Ws[(m0 + mt*16 + (lane&15))*LDE + ks*16 + ((lane>>4)&1)*8]));
                mma_bf16(acc[mt][0], Av, Bv);
                mma_bf16(acc[mt][1], Av, Bv+2);
            }
        }
        #pragma unroll
        for(int mt=0; mt<2; ++mt){
            int r0 = m0 + mt*16 + (lane>>2);
            float bb0 = b1[r0], bb1 = b1[r0+8];
            #pragma unroll
            for(int nh=0; nh<2; ++nh){
                int cc = n + nh*8 + (lane&3)*2;
                float v00 = gelu_f(acc[mt][nh][0] + bb0);
                float v01 = gelu_f(acc[mt][nh][1] + bb0);
                float v10 = gelu_f(acc[mt][nh][2] + bb1);
                float v11 = gelu_f(acc[mt][nh][3] + bb1);
                *(__nv_bfloat162*)(hidb + (size_t)r0*N_ + cc)     = __floats2bfloat162_rn(v00, v01);
                *(__nv_bfloat162*)(hidb + (size_t)(r0+8)*N_ + cc) = __floats2bfloat162_rn(v10, v11);
            }
        }
    }
}

// ---------------- K6: z = x1 + W2 hid + b2, LN2 stats ----------------------
// grid (512 n-tiles of 64, 8), 256 thr
__global__ void __launch_bounds__(256) k_mlp2(const float* __restrict__ b2){
    extern __shared__ __nv_bfloat16 sm6[];
    __nv_bfloat16* Ws = sm6;               // [128][LDW2]
    __nv_bfloat16* Hs = sm6 + C_*LDW2;     // [128][LDH]
    int b = blockIdx.y, n0 = blockIdx.x*64;
    int tid = threadIdx.x, lane = tid&31, warp = tid>>5;
    for(int idx=tid; idx<8192; idx+=256){   // W2 128x512 bf16
        int r = idx>>6, c8 = (idx&63)*8;
        *(uint4*)&Ws[r*LDW2 + c8] = *(const uint4*)&g_W2[r*MLP_ + c8];
    }
    const __nv_bfloat16* hidb = g_hid + (size_t)b*MLP_*N_ + n0;
    float acc[8][4] = {};
    int m0 = warp*16;
    for(int kc=0; kc<4; ++kc){
        __syncthreads();
        for(int idx=tid; idx<1024; idx+=256){   // hid chunk 128x64
            int r = idx>>3, c8 = (idx&7)*8;
            *(uint4*)&Hs[r*LDH + c8] = *(const uint4*)(hidb + (size_t)(kc*128 + r)*N_ + c8);
        }
        __syncthreads();
        #pragma unroll
        for(int ks=0; ks<8; ++ks){
            uint32_t Av[4];
            ldsmx4(Av, s2u(&Ws[(m0 + (lane&15))*LDW2 + kc*128 + ks*16 + ((lane>>4)&1)*8]));
            #pragma unroll
            for(int nt=0; nt<4; ++nt){
                uint32_t Bv[4];
                ldsmx4t(Bv, s2u(&Hs[(ks*16 + (lane&7) + ((lane>>3)&1)*8)*LDH + nt*16 + ((lane>>4)&1)*8]));
                mma_bf16(acc[nt*2+0], Av, Bv);
                mma_bf16(acc[nt*2+1], Av, Bv+2);
            }
        }
    }
    const float* x1b = g_x1 + (size_t)b*NEL + n0;
    float* zb = g_y + (size_t)b*NEL + n0;   // reuse g_y as z
    int r0 = m0 + (lane>>2);
    float bb0 = b2[r0], bb1 = b2[r0+8];
    float ls = 0.f, lq = 0.f;
    #pragma unroll
    for(int nt=0; nt<4; ++nt){
        #pragma unroll
        for(int nh=0; nh<2; ++nh){
            int cc = nt*16 + nh*8 + (lane&3)*2;
            float2 xa = *(const float2*)(x1b + (size_t)r0*N_ + cc);
            float2 xc = *(const float2*)(x1b + (size_t)(r0+8)*N_ + cc);
            float* a = acc[nt*2+nh];
            float z00 = xa.x + a[0] + bb0;
            float z01 = xa.y + a[1] + bb0;
            float z10 = xc.x + a[2] + bb1;
            float z11 = xc.y + a[3] + bb1;
            *(float2*)(zb + (size_t)r0*N_ + cc)     = make_float2(z00, z01);
            *(float2*)(zb + (size_t)(r0+8)*N_ + cc) = make_float2(z10, z11);
            ls += z00+z01+z10+z11;
            lq += z00*z00 + z01*z01 + z10*z10 + z11*z11;
        }
    }
    #pragma unroll
    for(int o=16;o>0;o>>=1){ ls += __shfl_xor_sync(0xffffffffu, ls, o);
                             lq += __shfl_xor_sync(0xffffffffu, lq, o); }
    if(lane==0){ atomicAdd(&g_stats[2][b], ls); atomicAdd(&g_stats[3][b], lq); }
}

// ---------------- K8: out = LN2(z) -----------------------------------------
__global__ void __launch_bounds__(256) k_out(const float* __restrict__ w,
                                             const float* __restrict__ bb,
                                             float* __restrict__ out){
    size_t nv = (size_t)B_*NEL/4;
    size_t st = (size_t)gridDim.x*blockDim.x;
    for(size_t v = (size_t)blockIdx.x*blockDim.x + threadIdx.x; v < nv; v += st){
        size_t t = v*4;
        int b = (int)(t / NEL);
        size_t r = t - (size_t)b*NEL;
        float mu = g_norm[2][b], rs = g_norm[3][b];
        float4 z  = *(const float4*)(g_y + t);
        float4 wv = *(const float4*)(w + r);
        float4 bv = *(const float4*)(bb + r);
        float4 o;
        o.x = (z.x-mu)*rs*wv.x + bv.x;
        o.y = (z.y-mu)*rs*wv.y + bv.y;
        o.z = (z.z-mu)*rs*wv.z + bv.z;
        o.w = (z.w-mu)*rs*wv.w + bv.w;
        *(float4*)(out + t) = o;
    }
}

// ---------------- launch ----------------------------------------------------
extern "C" void kernel_launch(void* const* d_in, const int* in_sizes, int n_in,
                              void* d_out, int out_size){
    const float* x      = (const float*)d_in[0];
    const float* qkv_w  = (const float*)d_in[1];
    const float* proj_w = (const float*)d_in[2];
    const float* proj_b = (const float*)d_in[3];
    const float* ln1w   = (const float*)d_in[4];
    const float* ln1b   = (const float*)d_in[5];
    const float* ln2w   = (const float*)d_in[6];
    const float* ln2b   = (const float*)d_in[7];
    const float* w1     = (const float*)d_in[8];
    const float* b1     = (const float*)d_in[9];
    const float* w2     = (const float*)d_in[10];
    const float* b2     = (const float*)d_in[11];
    float* out = (float*)d_out;

    cudaFuncSetAttribute(k_attn, cudaFuncAttributeMaxDynamicSharedMemorySize, 139264);
    cudaFuncSetAttribute(k_apply, cudaFuncAttributeMaxDynamicSharedMemorySize, 69632);
    cudaFuncSetAttribute(k_mlp1, cudaFuncAttributeMaxDynamicSharedMemorySize, 174080);
    cudaFuncSetAttribute(k_mlp2, cudaFuncAttributeMaxDynamicSharedMemorySize, 151552);

    k_init<<<256, 256>>>(w1, w2);
    k_gram<<<dim3(64, 8), 256>>>(x);
    k_attn<<<8, 512, 139264>>>(qkv_w, proj_w);
    k_apply<<<dim3(256, 8), 256, 69632>>>(x, proj_b);
    k_norm<<<1, 32>>>(0);
    k_mlp1<<<dim3(256, 8), 512, 174080>>>(ln1w, ln1b, b1);
    k_mlp2<<<dim3(512, 8), 256, 151552>>>(b2);
    k_norm<<<1, 32>>>(1);
    k_out<<<8192, 256>>>(ln2w, ln2b, out);
}

// round 4
// speedup vs baseline: 1.5083x; 1.5083x over previous
#include <cuda_runtime.h>
#include <cuda_bf16.h>
#include <cstdint>
#include <math.h>

#define B_ 8
#define C_ 128
#define N_ 32768
#define NEL 4194304
#define MLP_ 512
#define EPS_ 1e-5f
#define SCALE_ 0.25f
#define LDE 136
#define LDH 136
#define LDX 132
#define GLD 72

// ---------------- scratch (device globals; no runtime allocation) ----------
__device__ float         g_G[B_][C_][C_];
__device__ float         g_T[B_][C_][C_];   // T1 transposed: [t][i]
__device__ float         g_M[B_][C_][C_];
__device__ float         g_A[B_][C_][16];
__device__ __nv_bfloat16 g_E[B_][C_][C_];
__device__ float         g_stats[4][B_];
__device__ float         g_norm[4][B_];
__device__ __nv_bfloat16 g_W1[MLP_*C_];
__device__ __nv_bfloat16 g_W2[C_*MLP_];
__device__ float         g_y [(size_t)B_*NEL];   // y, later reused as z

// ---------------- helpers ----------------
__device__ __forceinline__ uint32_t s2u(const void* p){
    return (uint32_t)__cvta_generic_to_shared(p);
}
__device__ __forceinline__ void ldsmx4(uint32_t* r, uint32_t a){
    asm volatile("ldmatrix.sync.aligned.m8n8.x4.shared.b16 {%0,%1,%2,%3},[%4];"
        : "=r"(r[0]),"=r"(r[1]),"=r"(r[2]),"=r"(r[3]) : "r"(a));
}
__device__ __forceinline__ void ldsmx4t(uint32_t* r, uint32_t a){
    asm volatile("ldmatrix.sync.aligned.m8n8.x4.trans.shared.b16 {%0,%1,%2,%3},[%4];"
        : "=r"(r[0]),"=r"(r[1]),"=r"(r[2]),"=r"(r[3]) : "r"(a));
}
__device__ __forceinline__ void mma_bf16(float* c, const uint32_t* a, const uint32_t* b){
    asm volatile("mma.sync.aligned.m16n8k16.row.col.f32.bf16.bf16.f32 "
        "{%0,%1,%2,%3},{%4,%5,%6,%7},{%8,%9},{%0,%1,%2,%3};"
        : "+f"(c[0]),"+f"(c[1]),"+f"(c[2]),"+f"(c[3])
        : "r"(a[0]),"r"(a[1]),"r"(a[2]),"r"(a[3]),"r"(b[0]),"r"(b[1]));
}
__device__ __forceinline__ float gelu_f(float v){
    return 0.5f*v*(1.0f+erff(v*0.70710678118654752f));
}

// ---------------- K0: zero scratch, convert MLP weights to bf16 ------------
__global__ void k_init(const float* __restrict__ w1, const float* __restrict__ w2){
    int i  = blockIdx.x*blockDim.x + threadIdx.x;
    int st = gridDim.x*blockDim.x;
    float* gg = &g_G[0][0][0];
    for(int t=i; t<B_*C_*C_; t+=st) gg[t] = 0.f;
    float* gs = &g_stats[0][0];
    for(int t=i; t<4*B_; t+=st) gs[t] = 0.f;
    for(int t=i; t<MLP_*C_; t+=st) g_W1[t] = __float2bfloat16(w1[t]);
    for(int t=i; t<C_*MLP_; t+=st) g_W2[t] = __float2bfloat16(w2[t]);
}

// ---------------- K1: per-batch Gram matrix G = X X^T ----------------------
__global__ void __launch_bounds__(256) k_gram(const float* __restrict__ x){
    __shared__ __nv_bfloat16 Xs[C_][GLD];
    int b = blockIdx.y, split = blockIdx.x;
    const float* xb = x + (size_t)b*NEL + split*512;
    int tid = threadIdx.x, lane = tid&31, warp = tid>>5;
    float acc[16][4];
    #pragma unroll
    for(int i=0;i<16;++i){ acc[i][0]=acc[i][1]=acc[i][2]=acc[i][3]=0.f; }
    for(int kc=0; kc<8; ++kc){
        const float* src = xb + kc*64;
        for(int idx=tid; idx<2048; idx+=256){
            int row = idx>>4, c4 = idx&15;
            float4 v = *(const float4*)(src + (size_t)row*N_ + c4*4);
            __nv_bfloat162* d = (__nv_bfloat162*)&Xs[row][c4*4];
            d[0] = __floats2bfloat162_rn(v.x, v.y);
            d[1] = __floats2bfloat162_rn(v.z, v.w);
        }
        __syncthreads();
        int m0 = warp*16;
        #pragma unroll
        for(int ks=0; ks<4; ++ks){
            int k = ks*16;
            uint32_t a[4];
            ldsmx4(a, s2u(&Xs[m0 + (lane&15)][k + ((lane>>4)&1)*8]));
            #pragma unroll
            for(int nt=0; nt<8; ++nt){
                uint32_t Bv[4];
                ldsmx4(Bv, s2u(&Xs[nt*16 + (lane&7) + ((lane>>4)&1)*8][k + ((lane>>3)&1)*8]));
                mma_bf16(acc[nt*2+0], a, Bv);
                mma_bf16(acc[nt*2+1], a, Bv+2);
            }
        }
        __syncthreads();
    }
    float* Gb = &g_G[b][0][0];
    int r0 = warp*16 + (lane>>2);
    #pragma unroll
    for(int nt=0; nt<16; ++nt){
        int c0 = nt*8 + (lane&3)*2;
        atomicAdd(&Gb[(size_t)r0*C_ + c0],       acc[nt][0]);
        atomicAdd(&Gb[(size_t)r0*C_ + c0+1],     acc[nt][1]);
        atomicAdd(&Gb[(size_t)(r0+8)*C_ + c0],   acc[nt][2]);
        atomicAdd(&Gb[(size_t)(r0+8)*C_ + c0+1], acc[nt][3]);
    }
}

// ---------------- K2a: T1[t][i] = sum_k Wq[i][k] * G[k][t] (transposed out)
__global__ void __launch_bounds__(256) k_att_a(const float* __restrict__ qkv_w){
    int b = blockIdx.y;
    int t = blockIdx.x*16 + (threadIdx.x&15);
    int ig = threadIdx.x>>4;
    float acc[8] = {0.f,0.f,0.f,0.f,0.f,0.f,0.f,0.f};
    for(int k=0;k<C_;++k){
        float gv = g_G[b][k][t];
        #pragma unroll
        for(int ii=0;ii<8;++ii)
            acc[ii] += qkv_w[(size_t)(ig + ii*16)*C_ + k] * gv;
    }
    #pragma unroll
    for(int ii=0;ii<8;++ii)
        g_T[b][t][ig + ii*16] = acc[ii];
}

// ---------------- K2b: logits + softmax -> A -------------------------------
__global__ void __launch_bounds__(128) k_att_b(const float* __restrict__ qkv_w){
    int b = blockIdx.x, i = threadIdx.x;
    int h = i>>4;
    float acc[16];
    #pragma unroll
    for(int j=0;j<16;++j) acc[j]=0.f;
    for(int t=0;t<C_;++t){
        float tv = g_T[b][t][i];
        #pragma unroll
        for(int j=0;j<16;++j)
            acc[j] += tv * qkv_w[(size_t)(C_ + h*16 + j)*C_ + t];
    }
    float mx = -1e30f;
    #pragma unroll
    for(int j=0;j<16;++j){ acc[j]*=SCALE_; mx = fmaxf(mx, acc[j]); }
    float s = 0.f;
    #pragma unroll
    for(int j=0;j<16;++j){ acc[j] = expf(acc[j]-mx); s += acc[j]; }
    float inv = 1.f/s;
    #pragma unroll
    for(int j=0;j<16;++j) g_A[b][i][j] = acc[j]*inv;
}

// ---------------- K2c: M[r][k] = sum_j A[r][j] * Wv[h*16+j][k] -------------
__global__ void __launch_bounds__(256) k_att_c(const float* __restrict__ qkv_w){
    int b = blockIdx.y;
    int k = blockIdx.x*16 + (threadIdx.x&15);
    int rg = threadIdx.x>>4;
    #pragma unroll
    for(int ri=0;ri<8;++ri){
        int r = rg + ri*16;
        int h = r>>4;
        float a = 0.f;
        #pragma unroll
        for(int j=0;j<16;++j)
            a += g_A[b][r][j] * qkv_w[(size_t)(2*C_ + h*16 + j)*C_ + k];
        g_M[b][r][k] = a;
    }
}

// ---------------- K2d: E[o][k] = sum_r Wp[o][r] * M[r][k] -> bf16 ----------
__global__ void __launch_bounds__(256) k_att_d(const float* __restrict__ proj_w){
    int b = blockIdx.y;
    int k = blockIdx.x*16 + (threadIdx.x&15);
    int og = threadIdx.x>>4;
    float acc[8] = {0.f,0.f,0.f,0.f,0.f,0.f,0.f,0.f};
    for(int r=0;r<C_;++r){
        float mv = g_M[b][r][k];
        #pragma unroll
        for(int ii=0;ii<8;++ii)
            acc[ii] += proj_w[(size_t)(og + ii*16)*C_ + r] * mv;
    }
    #pragma unroll
    for(int ii=0;ii<8;++ii)
        g_E[b][og + ii*16][k] = __float2bfloat16(acc[ii]);
}

// ---------------- K3: y = x + E*x + proj_b, LN1 stats ----------------------
// grid (256, 8), 512 thr, 2 CTAs/SM
__global__ void __launch_bounds__(512) k_apply(const float* __restrict__ x,
                                               const float* __restrict__ proj_b){
    extern __shared__ __nv_bfloat16 sm3[];
    __nv_bfloat16* Es = sm3;              // [128][LDE]
    __nv_bfloat16* Xs = sm3 + C_*LDE;     // [128][LDE]
    int b = blockIdx.y, n0 = blockIdx.x*128;
    int tid = threadIdx.x, lane = tid&31, warp = tid>>5;
    const float* xb = x + (size_t)b*NEL + n0;
    for(int idx=tid; idx<2048; idx+=512){
        int r = idx>>4, c8 = (idx&15)*8;
        *(uint4*)&Es[r*LDE + c8] = *(const uint4*)&g_E[b][r][c8];
    }
    for(int idx=tid; idx<4096; idx+=512){
        int r = idx>>5, c4 = (idx&31)*4;
        float4 v = *(const float4*)(xb + (size_t)r*N_ + c4);
        __nv_bfloat162* d = (__nv_bfloat162*)&Xs[r*LDE + c4];
        d[0] = __floats2bfloat162_rn(v.x, v.y);
        d[1] = __floats2bfloat162_rn(v.z, v.w);
    }
    __syncthreads();
    int mw = warp&7, nw = warp>>3;
    int m0 = mw*16;
    uint32_t A8[8][4];
    #pragma unroll
    for(int ks=0; ks<8; ++ks)
        ldsmx4(A8[ks], s2u(&Es[(m0 + (lane&15))*LDE + ks*16 + ((lane>>4)&1)*8]));
    float* yb = g_y + (size_t)b*NEL + n0;
    int r0 = m0 + (lane>>2);
    float pb0 = proj_b[r0], pb1 = proj_b[r0+8];
    float ls = 0.f, lq = 0.f;
    for(int ns=0; ns<4; ++ns){
        int n = nw*64 + ns*16;
        float acc[2][4] = {};
        #pragma unroll
        for(int ks=0; ks<8; ++ks){
            uint32_t Bv[4];
            ldsmx4t(Bv, s2u(&Xs[(ks*16 + (lane&7) + ((lane>>3)&1)*8)*LDE + n + ((lane>>4)&1)*8]));
            mma_bf16(acc[0], A8[ks], Bv);
            mma_bf16(acc[1], A8[ks], Bv+2);
        }
        #pragma unroll
        for(int nh=0; nh<2; ++nh){
            int cc = n + nh*8 + (lane&3)*2;
            float2 x0  = *(const float2*)(xb + (size_t)r0*N_ + cc);
            float2 x1v = *(const float2*)(xb + (size_t)(r0+8)*N_ + cc);
            float y00 = x0.x  + acc[nh][0] + pb0;
            float y01 = x0.y  + acc[nh][1] + pb0;
            float y10 = x1v.x + acc[nh][2] + pb1;
            float y11 = x1v.y + acc[nh][3] + pb1;
            *(float2*)(yb + (size_t)r0*N_ + cc)     = make_float2(y00, y01);
            *(float2*)(yb + (size_t)(r0+8)*N_ + cc) = make_float2(y10, y11);
            ls += y00+y01+y10+y11;
            lq += y00*y00 + y01*y01 + y10*y10 + y11*y11;
        }
    }
    #pragma unroll
    for(int o=16;o>0;o>>=1){ ls += __shfl_xor_sync(0xffffffffu, ls, o);
                             lq += __shfl_xor_sync(0xffffffffu, lq, o); }
    if(lane==0){ atomicAdd(&g_stats[0][b], ls); atomicAdd(&g_stats[1][b], lq); }
}

// ---------------- K4/K7: finalize LN stats ---------------------------------
__global__ void k_norm(int stage){
    int b = threadIdx.x;
    if(b < B_){
        float s = g_stats[stage*2][b], q = g_stats[stage*2+1][b];
        float mu = s / (float)NEL;
        float var = q / (float)NEL - mu*mu;
        g_norm[stage*2][b]   = mu;
        g_norm[stage*2+1][b] = rsqrtf(var + EPS_);
    }
}

// ---------------- K5: fused MLP: x1=LN1(y); z = x1 + W2 gelu(W1 x1 + b1) + b2
// grid (256, 8), 512 thr, hid lives in smem (two halves of 256 channels)
__global__ void __launch_bounds__(512) k_mlp(const float* __restrict__ ln1w,
                                             const float* __restrict__ ln1b,
                                             const float* __restrict__ b1,
                                             const float* __restrict__ b2){
    extern __shared__ char smraw[];
    float*         X1f = (float*)smraw;                            // 128*132*4
    __nv_bfloat16* Xs  = (__nv_bfloat16*)(smraw + C_*LDX*4);       // 128*136*2
    __nv_bfloat16* Hs  = (__nv_bfloat16*)(smraw + C_*LDX*4 + C_*LDH*2); // 256*136*2
    int b = blockIdx.y, n0 = blockIdx.x*128;
    int tid = threadIdx.x, lane = tid&31, warp = tid>>5;
    float mu = g_norm[0][b], rs = g_norm[1][b];
    const float* yb = g_y + (size_t)b*NEL + n0;
    for(int idx=tid; idx<4096; idx+=512){
        int r = idx>>5, c4 = (idx&31)*4;
        size_t off = (size_t)r*N_ + c4;
        float4 y4 = *(const float4*)(yb + off);
        float4 w4 = *(const float4*)(ln1w + (size_t)r*N_ + n0 + c4);
        float4 b4 = *(const float4*)(ln1b + (size_t)r*N_ + n0 + c4);
        float4 o;
        o.x = (y4.x-mu)*rs*w4.x + b4.x;
        o.y = (y4.y-mu)*rs*w4.y + b4.y;
        o.z = (y4.z-mu)*rs*w4.z + b4.z;
        o.w = (y4.w-mu)*rs*w4.w + b4.w;
        *(float4*)&X1f[r*LDX + c4] = o;
        __nv_bfloat162* d = (__nv_bfloat162*)&Xs[r*LDH + c4];
        d[0] = __floats2bfloat162_rn(o.x, o.y);
        d[1] = __floats2bfloat162_rn(o.z, o.w);
    }
    __syncthreads();
    int ar = lane>>2, ac = (lane&3)*2;
    int mw2 = warp&3, nw2 = warp>>2;   // 4x4 for GEMM2
    float zacc[2][4][4];
    #pragma unroll
    for(int a=0;a<2;++a)
        #pragma unroll
        for(int c=0;c<4;++c){ zacc[a][c][0]=zacc[a][c][1]=zacc[a][c][2]=zacc[a][c][3]=0.f; }
    for(int h=0; h<2; ++h){
        // ---- GEMM1: hid_half = gelu(W1_half * x1 + b1); 16 warps x 16 rows
        int ch0 = h*256 + warp*16;
        uint32_t Wf[8][4];
        const __nv_bfloat16* w1p = g_W1 + (size_t)ch0*C_;
        #pragma unroll
        for(int ks=0;ks<8;++ks){
            const __nv_bfloat16* wp = w1p + ks*16;
            Wf[ks][0] = *(const uint32_t*)(wp + (size_t)(ar  )*C_ + ac);
            Wf[ks][1] = *(const uint32_t*)(wp + (size_t)(ar+8)*C_ + ac);
            Wf[ks][2] = *(const uint32_t*)(wp + (size_t)(ar  )*C_ + ac + 8);
            Wf[ks][3] = *(const uint32_t*)(wp + (size_t)(ar+8)*C_ + ac + 8);
        }
        float bb0 = b1[ch0 + ar], bb1 = b1[ch0 + ar + 8];
        int hr = warp*16 + ar;
        for(int ns=0; ns<8; ++ns){
            float acc[2][4] = {};
            #pragma unroll
            for(int ks=0;ks<8;++ks){
                uint32_t Bv[4];
                ldsmx4t(Bv, s2u(&Xs[(ks*16 + (lane&7) + ((lane>>3)&1)*8)*LDH + ns*16 + ((lane>>4)&1)*8]));
                mma_bf16(acc[0], Wf[ks], Bv);
                mma_bf16(acc[1], Wf[ks], Bv+2);
            }
            #pragma unroll
            for(int nh=0; nh<2; ++nh){
                int cc = ns*16 + nh*8 + ac;
                *(__nv_bfloat162*)&Hs[hr*LDH + cc] =
                    __floats2bfloat162_rn(gelu_f(acc[nh][0]+bb0), gelu_f(acc[nh][1]+bb0));
                *(__nv_bfloat162*)&Hs[(hr+8)*LDH + cc] =
                    __floats2bfloat162_rn(gelu_f(acc[nh][2]+bb1), gelu_f(acc[nh][3]+bb1));
            }
        }
        __syncthreads();
        // ---- GEMM2 partial: z += W2[:, half] * hid_half; warps 4mw x 4nw
        const __nv_bfloat16* w2p = g_W2 + (size_t)(mw2*32)*MLP_ + h*256;
        #pragma unroll 4
        for(int kc=0; kc<16; ++kc){
            uint32_t Af[2][4];
            #pragma unroll
            for(int mt=0; mt<2; ++mt){
                const __nv_bfloat16* wp = w2p + (size_t)(mt*16)*MLP_ + kc*16;
                Af[mt][0] = *(const uint32_t*)(wp + (size_t)(ar  )*MLP_ + ac);
                Af[mt][1] = *(const uint32_t*)(wp + (size_t)(ar+8)*MLP_ + ac);
                Af[mt][2] = *(const uint32_t*)(wp + (size_t)(ar  )*MLP_ + ac + 8);
                Af[mt][3] = *(const uint32_t*)(wp + (size_t)(ar+8)*MLP_ + ac + 8);
            }
            #pragma unroll
            for(int nt=0; nt<2; ++nt){
                uint32_t Bv[4];
                ldsmx4t(Bv, s2u(&Hs[(kc*16 + (lane&7) + ((lane>>3)&1)*8)*LDH + nw2*32 + nt*16 + ((lane>>4)&1)*8]));
                #pragma unroll
                for(int mt=0; mt<2; ++mt){
                    mma_bf16(zacc[mt][nt*2+0], Af[mt], Bv);
                    mma_bf16(zacc[mt][nt*2+1], Af[mt], Bv+2);
                }
            }
        }
        __syncthreads();
    }
    // ---- epilogue: z = x1 + zacc + b2; LN2 stats
    float* zb = g_y + (size_t)b*NEL + n0;
    float ls = 0.f, lq = 0.f;
    #pragma unroll
    for(int mt=0; mt<2; ++mt){
        int r0 = mw2*32 + mt*16 + ar;
        float bz0 = b2[r0], bz1 = b2[r0+8];
        #pragma unroll
        for(int n8=0; n8<4; ++n8){
            int cc = nw2*32 + n8*8 + ac;
            float2 xa = *(const float2*)&X1f[r0*LDX + cc];
            float2 xc = *(const float2*)&X1f[(r0+8)*LDX + cc];
            float* a = zacc[mt][n8];
            float z00 = xa.x + a[0] + bz0;
            float z01 = xa.y + a[1] + bz0;
            float z10 = xc.x + a[2] + bz1;
            float z11 = xc.y + a[3] + bz1;
            *(float2*)(zb + (size_t)r0*N_ + cc)     = make_float2(z00, z01);
            *(float2*)(zb + (size_t)(r0+8)*N_ + cc) = make_float2(z10, z11);
            ls += z00+z01+z10+z11;
            lq += z00*z00 + z01*z01 + z10*z10 + z11*z11;
        }
    }
    #pragma unroll
    for(int o=16;o>0;o>>=1){ ls += __shfl_xor_sync(0xffffffffu, ls, o);
                             lq += __shfl_xor_sync(0xffffffffu, lq, o); }
    if(lane==0){ atomicAdd(&g_stats[2][b], ls); atomicAdd(&g_stats[3][b], lq); }
}

// ---------------- K8: out = LN2(z), ln2 params read once -------------------
__global__ void __launch_bounds__(256) k_out(const float* __restrict__ w,
                                             const float* __restrict__ bb,
                                             float* __restrict__ out){
    size_t nv = (size_t)NEL/4;
    size_t st = (size_t)gridDim.x*blockDim.x;
    for(size_t v = (size_t)blockIdx.x*blockDim.x + threadIdx.x; v < nv; v += st){
        size_t t = v*4;
        float4 wv = *(const float4*)(w + t);
        float4 bv = *(const float4*)(bb + t);
        #pragma unroll
        for(int b=0;b<B_;++b){
            float mu = g_norm[2][b], rs = g_norm[3][b];
            float4 z  = *(const float4*)(g_y + (size_t)b*NEL + t);
            float4 o;
            o.x = (z.x-mu)*rs*wv.x + bv.x;
            o.y = (z.y-mu)*rs*wv.y + bv.y;
            o.z = (z.z-mu)*rs*wv.z + bv.z;
            o.w = (z.w-mu)*rs*wv.w + bv.w;
            *(float4*)(out + (size_t)b*NEL + t) = o;
        }
    }
}

// ---------------- launch ----------------------------------------------------
extern "C" void kernel_launch(void* const* d_in, const int* in_sizes, int n_in,
                              void* d_out, int out_size){
    const float* x      = (const float*)d_in[0];
    const float* qkv_w  = (const float*)d_in[1];
    const float* proj_w = (const float*)d_in[2];
    const float* proj_b = (const float*)d_in[3];
    const float* ln1w   = (const float*)d_in[4];
    const float* ln1b   = (const float*)d_in[5];
    const float* ln2w   = (const float*)d_in[6];
    const float* ln2b   = (const float*)d_in[7];
    const float* w1     = (const float*)d_in[8];
    const float* b1     = (const float*)d_in[9];
    const float* w2     = (const float*)d_in[10];
    const float* b2     = (const float*)d_in[11];
    float* out = (float*)d_out;

    const int SM_APPLY = 2*C_*LDE*2;                 // 69632
    const int SM_MLP   = C_*LDX*4 + C_*LDH*2 + 2*C_*LDH*2;  // 172032
    cudaFuncSetAttribute(k_apply, cudaFuncAttributeMaxDynamicSharedMemorySize, SM_APPLY);
    cudaFuncSetAttribute(k_mlp,   cudaFuncAttributeMaxDynamicSharedMemorySize, SM_MLP);

    k_init<<<256, 256>>>(w1, w2);
    k_gram<<<dim3(64, 8), 256>>>(x);
    k_att_a<<<dim3(8, 8), 256>>>(qkv_w);
    k_att_b<<<8, 128>>>(qkv_w);
    k_att_c<<<dim3(8, 8), 256>>>(qkv_w);
    k_att_d<<<dim3(8, 8), 256>>>(proj_w);
    k_apply<<<dim3(256, 8), 512, SM_APPLY>>>(x, proj_b);
    k_norm<<<1, 32>>>(0);
    k_mlp<<<dim3(256, 8), 512, SM_MLP>>>(ln1w, ln1b, b1, b2);
    k_norm<<<1, 32>>>(1);
    k_out<<<4096, 256>>>(ln2w, ln2b, out);
}

// round 5
// speedup vs baseline: 1.6432x; 1.0894x over previous
#include <cuda_runtime.h>
#include <cuda_bf16.h>
#include <cstdint>
#include <math.h>

#define B_ 8
#define C_ 128
#define N_ 32768
#define NEL 4194304
#define MLP_ 512
#define EPS_ 1e-5f
#define SCALE_ 0.25f
#define LDE 136
#define LDH 136
#define LDX 132
#define GLD 72

// ---------------- scratch (device globals; no runtime allocation) ----------
__device__ float         g_G[B_][C_][C_];
__device__ float         g_M[B_][C_][C_];
__device__ float         g_s[B_][C_];       // row sums of x (fp32)
__device__ float         g_Ef[B_][C_][C_];  // E fp32
__device__ __nv_bfloat16 g_E[B_][C_][C_];
__device__ float         g_stats[4][B_];
__device__ float         g_norm[4][B_];
__device__ __nv_bfloat16 g_W1[MLP_*C_];
__device__ __nv_bfloat16 g_W2[C_*MLP_];
__device__ float         g_y [(size_t)B_*NEL];   // z buffer

// ---------------- helpers ----------------
__device__ __forceinline__ uint32_t s2u(const void* p){
    return (uint32_t)__cvta_generic_to_shared(p);
}
__device__ __forceinline__ void ldsmx4(uint32_t* r, uint32_t a){
    asm volatile("ldmatrix.sync.aligned.m8n8.x4.shared.b16 {%0,%1,%2,%3},[%4];"
        : "=r"(r[0]),"=r"(r[1]),"=r"(r[2]),"=r"(r[3]) : "r"(a));
}
__device__ __forceinline__ void ldsmx4t(uint32_t* r, uint32_t a){
    asm volatile("ldmatrix.sync.aligned.m8n8.x4.trans.shared.b16 {%0,%1,%2,%3},[%4];"
        : "=r"(r[0]),"=r"(r[1]),"=r"(r[2]),"=r"(r[3]) : "r"(a));
}
__device__ __forceinline__ void mma_bf16(float* c, const uint32_t* a, const uint32_t* b){
    asm volatile("mma.sync.aligned.m16n8k16.row.col.f32.bf16.bf16.f32 "
        "{%0,%1,%2,%3},{%4,%5,%6,%7},{%8,%9},{%0,%1,%2,%3};"
        : "+f"(c[0]),"+f"(c[1]),"+f"(c[2]),"+f"(c[3])
        : "r"(a[0]),"r"(a[1]),"r"(a[2]),"r"(a[3]),"r"(b[0]),"r"(b[1]));
}
__device__ __forceinline__ float gelu_f(float v){
    return 0.5f*v*(1.0f+erff(v*0.70710678118654752f));
}

// ---------------- K0: zero scratch, convert MLP weights -------------------
__global__ void k_init(const float* __restrict__ w1, const float* __restrict__ w2){
    int i  = blockIdx.x*blockDim.x + threadIdx.x;
    int st = gridDim.x*blockDim.x;
    float* gg = &g_G[0][0][0];
    for(int t=i; t<B_*C_*C_; t+=st) gg[t] = 0.f;
    float* gsv = &g_s[0][0];
    for(int t=i; t<B_*C_; t+=st) gsv[t] = 0.f;
    float* gs = &g_stats[0][0];
    for(int t=i; t<4*B_; t+=st) gs[t] = 0.f;
    for(int t=i; t<MLP_*C_; t+=st) g_W1[t] = __float2bfloat16(w1[t]);
    for(int t=i; t<C_*MLP_; t+=st) g_W2[t] = __float2bfloat16(w2[t]);
}

// ---------------- K1: Gram G = X X^T  (+ row sums s) -----------------------
__global__ void __launch_bounds__(256) k_gram(const float* __restrict__ x){
    __shared__ __nv_bfloat16 Xs[C_][GLD];
    int b = blockIdx.y, split = blockIdx.x;
    const float* xb = x + (size_t)b*NEL + split*512;
    int tid = threadIdx.x, lane = tid&31, warp = tid>>5;
    float acc[16][4];
    #pragma unroll
    for(int i=0;i<16;++i){ acc[i][0]=acc[i][1]=acc[i][2]=acc[i][3]=0.f; }
    float racc[8] = {0.f,0.f,0.f,0.f,0.f,0.f,0.f,0.f};
    for(int kc=0; kc<8; ++kc){
        const float* src = xb + kc*64;
        #pragma unroll
        for(int m=0;m<8;++m){
            int idx = tid + m*256;
            int row = idx>>4, c4 = idx&15;
            float4 v = *(const float4*)(src + (size_t)row*N_ + c4*4);
            __nv_bfloat162* d = (__nv_bfloat162*)&Xs[row][c4*4];
            d[0] = __floats2bfloat162_rn(v.x, v.y);
            d[1] = __floats2bfloat162_rn(v.z, v.w);
            racc[m] += v.x+v.y+v.z+v.w;
        }
        __syncthreads();
        int m0 = warp*16;
        #pragma unroll
        for(int ks=0; ks<4; ++ks){
            int k = ks*16;
            uint32_t a[4];
            ldsmx4(a, s2u(&Xs[m0 + (lane&15)][k + ((lane>>4)&1)*8]));
            #pragma unroll
            for(int nt=0; nt<8; ++nt){
                uint32_t Bv[4];
                ldsmx4(Bv, s2u(&Xs[nt*16 + (lane&7) + ((lane>>4)&1)*8][k + ((lane>>3)&1)*8]));
                mma_bf16(acc[nt*2+0], a, Bv);
                mma_bf16(acc[nt*2+1], a, Bv+2);
            }
        }
        __syncthreads();
    }
    float* Gb = &g_G[b][0][0];
    int r0 = warp*16 + (lane>>2);
    #pragma unroll
    for(int nt=0; nt<16; ++nt){
        int c0 = nt*8 + (lane&3)*2;
        atomicAdd(&Gb[(size_t)r0*C_ + c0],       acc[nt][0]);
        atomicAdd(&Gb[(size_t)r0*C_ + c0+1],     acc[nt][1]);
        atomicAdd(&Gb[(size_t)(r0+8)*C_ + c0],   acc[nt][2]);
        atomicAdd(&Gb[(size_t)(r0+8)*C_ + c0+1], acc[nt][3]);
    }
    // row sums: reduce across the 16 lanes sharing each row
    #pragma unroll
    for(int m=0;m<8;++m){
        #pragma unroll
        for(int o=8;o>0;o>>=1)
            racc[m] += __shfl_xor_sync(0xffffffffu, racc[m], o, 16);
    }
    if((tid&15)==0){
        int rb = tid>>4;
        #pragma unroll
        for(int m=0;m<8;++m)
            atomicAdd(&g_s[b][rb + 16*m], racc[m]);
    }
}

// ---------------- K2: fused per-(batch,head) attention: T, softmax, M ------
__global__ void __launch_bounds__(256) k_att_qkm(const float* __restrict__ qkv_w){
    extern __shared__ float sq[];
    float* Gs  = sq;            // 16384
    float* Wqs = sq + 16384;    // 2112 (16 x 132)
    float* Wks = Wqs + 2112;
    float* Wvs = Wks + 2112;
    float* Ts  = Wvs + 2112;    // 2112
    float* As  = Ts + 2112;     // 256
    int h = blockIdx.x, b = blockIdx.y, tid = threadIdx.x;
    const float* Gb = &g_G[b][0][0];
    for(int i=tid;i<16384;i+=256) Gs[i] = Gb[i];
    for(int i=tid;i<2048;i+=256){
        int r=i>>7, c=i&127;
        Wqs[r*132+c] = qkv_w[(size_t)(h*16+r)*C_ + c];
        Wks[r*132+c] = qkv_w[(size_t)(C_+h*16+r)*C_ + c];
        Wvs[r*132+c] = qkv_w[(size_t)(2*C_+h*16+r)*C_ + c];
    }
    __syncthreads();
    int ii = tid>>4, tg = tid&15;
    {   // T[ii][t] = sum_k Wq[ii][k] G[k][t]
        float acc[8]={0.f,0.f,0.f,0.f,0.f,0.f,0.f,0.f};
        for(int k=0;k<C_;++k){
            float w = Wqs[ii*132+k];
            #pragma unroll
            for(int tt=0;tt<8;++tt) acc[tt] += w*Gs[k*128 + tg + tt*16];
        }
        #pragma unroll
        for(int tt=0;tt<8;++tt) Ts[ii*132 + tg + tt*16] = acc[tt];
    }
    __syncthreads();
    {   // logits + softmax (row = 16-lane group)
        float l = 0.f;
        #pragma unroll 4
        for(int t=0;t<C_;++t) l += Ts[ii*132+t]*Wks[tg*132+t];
        l *= SCALE_;
        float mx = l;
        #pragma unroll
        for(int o=8;o>0;o>>=1) mx = fmaxf(mx, __shfl_xor_sync(0xffffffffu, mx, o, 16));
        float e = expf(l-mx), s = e;
        #pragma unroll
        for(int o=8;o>0;o>>=1) s += __shfl_xor_sync(0xffffffffu, s, o, 16);
        As[ii*16+tg] = e/s;
    }
    __syncthreads();
    {   // M[ii][k] = sum_j A[ii][j] Wv[j][k]
        float acc[8]={0.f,0.f,0.f,0.f,0.f,0.f,0.f,0.f};
        #pragma unroll
        for(int j=0;j<16;++j){
            float a = As[ii*16+j];
            #pragma unroll
            for(int kk=0;kk<8;++kk) acc[kk] += a*Wvs[j*132 + tg + kk*16];
        }
        #pragma unroll
        for(int kk=0;kk<8;++kk) g_M[b][h*16+ii][tg+kk*16] = acc[kk];
    }
}

// ---------------- K3: E = Wp * M -> bf16 + fp32 ----------------------------
__global__ void __launch_bounds__(256) k_att_d(const float* __restrict__ proj_w){
    int b = blockIdx.y;
    int k = blockIdx.x*16 + (threadIdx.x&15);
    int og = threadIdx.x>>4;
    float acc[8] = {0.f,0.f,0.f,0.f,0.f,0.f,0.f,0.f};
    for(int r=0;r<C_;++r){
        float mv = g_M[b][r][k];
        #pragma unroll
        for(int ii=0;ii<8;++ii)
            acc[ii] += proj_w[(size_t)(og + ii*16)*C_ + r] * mv;
    }
    #pragma unroll
    for(int ii=0;ii<8;++ii){
        g_E [b][og + ii*16][k] = __float2bfloat16(acc[ii]);
        g_Ef[b][og + ii*16][k] = acc[ii];
    }
}

// ---------------- K4: analytic LN1 stats -----------------------------------
// sum(y)   = sum_c [(M s)_c + N*pb_c]
// sumsq(y) = sum_c [ M_c G M_c^T + 2 pb_c (M_c s) + N pb_c^2 ],  M = I + E
__global__ void __launch_bounds__(256) k_stats1(const float* __restrict__ proj_b){
    extern __shared__ float ss1[];
    float* Gs = ss1;          // 16384
    float* Ms = ss1+16384;    // 2112
    float* sv = Ms+2112;      // 128
    __shared__ float red[2][8];
    int rg = blockIdx.x, b = blockIdx.y, tid = threadIdx.x;
    const float* Gb = &g_G[b][0][0];
    for(int i=tid;i<16384;i+=256) Gs[i] = Gb[i];
    for(int i=tid;i<2048;i+=256){
        int r=i>>7, c=i&127;
        int cg = rg*16+r;
        Ms[r*132+c] = g_Ef[b][cg][c] + (cg==c ? 1.f : 0.f);
    }
    if(tid<128) sv[tid] = g_s[b][tid];
    __syncthreads();
    int cl = tid&15, jg = tid>>4;
    float qacc = 0.f, sacc = 0.f;
    #pragma unroll
    for(int jj=0;jj<8;++jj){
        int j = jg*8+jj;
        float p = 0.f;
        #pragma unroll 4
        for(int i=0;i<128;++i) p += Ms[cl*132+i]*Gs[i*128+j];
        qacc += p*Ms[cl*132+j];
    }
    if(jg==0){
        int c = rg*16+cl;
        float ms=0.f;
        #pragma unroll 4
        for(int i=0;i<128;++i) ms += Ms[cl*132+i]*sv[i];
        float pb = proj_b[c];
        sacc = ms + (float)N_*pb;
        qacc += 2.f*pb*ms + (float)N_*pb*pb;
    }
    #pragma unroll
    for(int o=16;o>0;o>>=1){
        qacc += __shfl_xor_sync(0xffffffffu,qacc,o);
        sacc += __shfl_xor_sync(0xffffffffu,sacc,o);
    }
    if((tid&31)==0){ red[0][tid>>5]=qacc; red[1][tid>>5]=sacc; }
    __syncthreads();
    if(tid==0){
        float q=0.f,s=0.f;
        #pragma unroll
        for(int w=0;w<8;++w){ q+=red[0][w]; s+=red[1][w]; }
        atomicAdd(&g_stats[1][b], q);
        atomicAdd(&g_stats[0][b], s);
    }
}

// ---------------- K5/K7: finalize LN stats ---------------------------------
__global__ void k_norm(int stage){
    int b = threadIdx.x;
    if(b < B_){
        float s = g_stats[stage*2][b], q = g_stats[stage*2+1][b];
        float mu = s / (float)NEL;
        float var = q / (float)NEL - mu*mu;
        g_norm[stage*2][b]   = mu;
        g_norm[stage*2+1][b] = rsqrtf(var + EPS_);
    }
}

// ---------------- K6: fused apply + LN1 + MLP ------------------------------
// y = x + E x + pb (regs); x1 = LN1(y); z = x1 + W2 gelu(W1 x1 + b1) + b2
__global__ void __launch_bounds__(512) k_am(const float* __restrict__ x,
                                            const float* __restrict__ proj_b,
                                            const float* __restrict__ ln1w,
                                            const float* __restrict__ ln1b,
                                            const float* __restrict__ b1,
                                            const float* __restrict__ b2){
    extern __shared__ char smraw[];
    __nv_bfloat16* EHs = (__nv_bfloat16*)smraw;                    // Es / Hs (69632 B)
    float*         X1f = (float*)(smraw + 69632);                  // 67584 B
    __nv_bfloat16* Xs  = (__nv_bfloat16*)(smraw + 69632 + 67584);  // 34816 B
    int b = blockIdx.y, n0 = blockIdx.x*128;
    int tid = threadIdx.x, lane = tid&31, warp = tid>>5;
    const float* xb = x + (size_t)b*NEL + n0;
    // load E (bf16) and x tile (bf16)
    for(int idx=tid; idx<2048; idx+=512){
        int r = idx>>4, c8 = (idx&15)*8;
        *(uint4*)&EHs[r*LDE + c8] = *(const uint4*)&g_E[b][r][c8];
    }
    for(int idx=tid; idx<4096; idx+=512){
        int r = idx>>5, c4 = (idx&31)*4;
        float4 v = *(const float4*)(xb + (size_t)r*N_ + c4);
        __nv_bfloat162* d = (__nv_bfloat162*)&Xs[r*LDH + c4];
        d[0] = __floats2bfloat162_rn(v.x, v.y);
        d[1] = __floats2bfloat162_rn(v.z, v.w);
    }
    __syncthreads();
    // ---- phase A: y = E*x + x + pb; x1 = LN1(y)  (in registers)
    int mw = warp&7, nw = warp>>3;
    int m0 = mw*16;
    int ar = lane>>2, ac = (lane&3)*2;
    uint32_t A8[8][4];
    #pragma unroll
    for(int ks=0; ks<8; ++ks)
        ldsmx4(A8[ks], s2u(&EHs[(m0 + (lane&15))*LDE + ks*16 + ((lane>>4)&1)*8]));
    int r0 = m0 + ar;
    float pb0 = proj_b[r0], pb1 = proj_b[r0+8];
    float mu1 = g_norm[0][b], rs1 = g_norm[1][b];
    float xv[4][2][4];
    for(int ns=0; ns<4; ++ns){
        int n = nw*64 + ns*16;
        float acc[2][4] = {};
        #pragma unroll
        for(int ks=0; ks<8; ++ks){
            uint32_t Bv[4];
            ldsmx4t(Bv, s2u(&Xs[(ks*16 + (lane&7) + ((lane>>3)&1)*8)*LDH + n + ((lane>>4)&1)*8]));
            mma_bf16(acc[0], A8[ks], Bv);
            mma_bf16(acc[1], A8[ks], Bv+2);
        }
        #pragma unroll
        for(int nh=0; nh<2; ++nh){
            int cc = n + nh*8 + ac;
            float2 x0  = *(const float2*)(xb + (size_t)r0*N_ + cc);
            float2 x1v = *(const float2*)(xb + (size_t)(r0+8)*N_ + cc);
            float y00 = x0.x  + acc[nh][0] + pb0;
            float y01 = x0.y  + acc[nh][1] + pb0;
            float y10 = x1v.x + acc[nh][2] + pb1;
            float y11 = x1v.y + acc[nh][3] + pb1;
            float2 w0 = *(const float2*)(ln1w + (size_t)r0*N_ + n0 + cc);
            float2 w1 = *(const float2*)(ln1w + (size_t)(r0+8)*N_ + n0 + cc);
            float2 g0 = *(const float2*)(ln1b + (size_t)r0*N_ + n0 + cc);
            float2 g1 = *(const float2*)(ln1b + (size_t)(r0+8)*N_ + n0 + cc);
            xv[ns][nh][0] = (y00-mu1)*rs1*w0.x + g0.x;
            xv[ns][nh][1] = (y01-mu1)*rs1*w0.y + g0.y;
            xv[ns][nh][2] = (y10-mu1)*rs1*w1.x + g1.x;
            xv[ns][nh][3] = (y11-mu1)*rs1*w1.y + g1.y;
        }
    }
    __syncthreads();   // all Xs / EHs reads done
    // ---- phase B: store x1 (fp32 + bf16)
    #pragma unroll
    for(int ns=0; ns<4; ++ns){
        #pragma unroll
        for(int nh=0; nh<2; ++nh){
            int cc = nw*64 + ns*16 + nh*8 + ac;
            *(float2*)&X1f[r0*LDX + cc]     = make_float2(xv[ns][nh][0], xv[ns][nh][1]);
            *(float2*)&X1f[(r0+8)*LDX + cc] = make_float2(xv[ns][nh][2], xv[ns][nh][3]);
            *(__nv_bfloat162*)&Xs[r0*LDH + cc]     = __floats2bfloat162_rn(xv[ns][nh][0], xv[ns][nh][1]);
            *(__nv_bfloat162*)&Xs[(r0+8)*LDH + cc] = __floats2bfloat162_rn(xv[ns][nh][2], xv[ns][nh][3]);
        }
    }
    __syncthreads();
    // ---- phase C: MLP (EHs region reused as Hs)
    __nv_bfloat16* Hs = EHs;
    int mw2 = warp&3, nw2 = warp>>2;
    float zacc[2][4][4];
    #pragma unroll
    for(int a=0;a<2;++a)
        #pragma unroll
        for(int c=0;c<4;++c){ zacc[a][c][0]=zacc[a][c][1]=zacc[a][c][2]=zacc[a][c][3]=0.f; }
    for(int h=0; h<2; ++h){
        int ch0 = h*256 + warp*16;
        uint32_t Wf[8][4];
        const __nv_bfloat16* w1p = g_W1 + (size_t)ch0*C_;
        #pragma unroll
        for(int ks=0;ks<8;++ks){
            const __nv_bfloat16* wp = w1p + ks*16;
            Wf[ks][0] = *(const uint32_t*)(wp + (size_t)(ar  )*C_ + ac);
            Wf[ks][1] = *(const uint32_t*)(wp + (size_t)(ar+8)*C_ + ac);
            Wf[ks][2] = *(const uint32_t*)(wp + (size_t)(ar  )*C_ + ac + 8);
            Wf[ks][3] = *(const uint32_t*)(wp + (size_t)(ar+8)*C_ + ac + 8);
        }
        float bb0 = b1[ch0 + ar], bb1 = b1[ch0 + ar + 8];
        int hr = warp*16 + ar;
        for(int ns=0; ns<8; ++ns){
            float acc[2][4] = {};
            #pragma unroll
            for(int ks=0;ks<8;++ks){
                uint32_t Bv[4];
                ldsmx4t(Bv, s2u(&Xs[(ks*16 + (lane&7) + ((lane>>3)&1)*8)*LDH + ns*16 + ((lane>>4)&1)*8]));
                mma_bf16(acc[0], Wf[ks], Bv);
                mma_bf16(acc[1], Wf[ks], Bv+2);
            }
            #pragma unroll
            for(int nh=0; nh<2; ++nh){
                int cc = ns*16 + nh*8 + ac;
                *(__nv_bfloat162*)&Hs[hr*LDH + cc] =
                    __floats2bfloat162_rn(gelu_f(acc[nh][0]+bb0), gelu_f(acc[nh][1]+bb0));
                *(__nv_bfloat162*)&Hs[(hr+8)*LDH + cc] =
                    __floats2bfloat162_rn(gelu_f(acc[nh][2]+bb1), gelu_f(acc[nh][3]+bb1));
            }
        }
        __syncthreads();
        const __nv_bfloat16* w2p = g_W2 + (size_t)(mw2*32)*MLP_ + h*256;
        #pragma unroll 4
        for(int kc=0; kc<16; ++kc){
            uint32_t Af[2][4];
            #pragma unroll
            for(int mt=0; mt<2; ++mt){
                const __nv_bfloat16* wp = w2p + (size_t)(mt*16)*MLP_ + kc*16;
                Af[mt][0] = *(const uint32_t*)(wp + (size_t)(ar  )*MLP_ + ac);
                Af[mt][1] = *(const uint32_t*)(wp + (size_t)(ar+8)*MLP_ + ac);
                Af[mt][2] = *(const uint32_t*)(wp + (size_t)(ar  )*MLP_ + ac + 8);
                Af[mt][3] = *(const uint32_t*)(wp + (size_t)(ar+8)*MLP_ + ac + 8);
            }
            #pragma unroll
            for(int nt=0; nt<2; ++nt){
                uint32_t Bv[4];
                ldsmx4t(Bv, s2u(&Hs[(kc*16 + (lane&7) + ((lane>>3)&1)*8)*LDH + nw2*32 + nt*16 + ((lane>>4)&1)*8]));
                #pragma unroll
                for(int mt=0; mt<2; ++mt){
                    mma_bf16(zacc[mt][nt*2+0], Af[mt], Bv);
                    mma_bf16(zacc[mt][nt*2+1], Af[mt], Bv+2);
                }
            }
        }
        __syncthreads();
    }
    // ---- epilogue: z = x1 + zacc + b2; LN2 stats
    float* zb = g_y + (size_t)b*NEL + n0;
    float ls = 0.f, lq = 0.f;
    #pragma unroll
    for(int mt=0; mt<2; ++mt){
        int rz = mw2*32 + mt*16 + ar;
        float bz0 = b2[rz], bz1 = b2[rz+8];
        #pragma unroll
        for(int n8=0; n8<4; ++n8){
            int cc = nw2*32 + n8*8 + ac;
            float2 xa = *(const float2*)&X1f[rz*LDX + cc];
            float2 xc = *(const float2*)&X1f[(rz+8)*LDX + cc];
            float* a = zacc[mt][n8];
            float z00 = xa.x + a[0] + bz0;
            float z01 = xa.y + a[1] + bz0;
            float z10 = xc.x + a[2] + bz1;
            float z11 = xc.y + a[3] + bz1;
            *(float2*)(zb + (size_t)rz*N_ + cc)     = make_float2(z00, z01);
            *(float2*)(zb + (size_t)(rz+8)*N_ + cc) = make_float2(z10, z11);
            ls += z00+z01+z10+z11;
            lq += z00*z00 + z01*z01 + z10*z10 + z11*z11;
        }
    }
    #pragma unroll
    for(int o=16;o>0;o>>=1){ ls += __shfl_xor_sync(0xffffffffu, ls, o);
                             lq += __shfl_xor_sync(0xffffffffu, lq, o); }
    if(lane==0){ atomicAdd(&g_stats[2][b], ls); atomicAdd(&g_stats[3][b], lq); }
}

// ---------------- K8: out = LN2(z) -----------------------------------------
__global__ void __launch_bounds__(256) k_out(const float* __restrict__ w,
                                             const float* __restrict__ bb,
                                             float* __restrict__ out){
    size_t nv = (size_t)NEL/4;
    size_t st = (size_t)gridDim.x*blockDim.x;
    for(size_t v = (size_t)blockIdx.x*blockDim.x + threadIdx.x; v < nv; v += st){
        size_t t = v*4;
        float4 wv = *(const float4*)(w + t);
        float4 bv = *(const float4*)(bb + t);
        #pragma unroll
        for(int b=0;b<B_;++b){
            float mu = g_norm[2][b], rs = g_norm[3][b];
            float4 z  = *(const float4*)(g_y + (size_t)b*NEL + t);
            float4 o;
            o.x = (z.x-mu)*rs*wv.x + bv.x;
            o.y = (z.y-mu)*rs*wv.y + bv.y;
            o.z = (z.z-mu)*rs*wv.z + bv.z;
            o.w = (z.w-mu)*rs*wv.w + bv.w;
            *(float4*)(out + (size_t)b*NEL + t) = o;
        }
    }
}

// ---------------- launch ----------------------------------------------------
extern "C" void kernel_launch(void* const* d_in, const int* in_sizes, int n_in,
                              void* d_out, int out_size){
    const float* x      = (const float*)d_in[0];
    const float* qkv_w  = (const float*)d_in[1];
    const float* proj_w = (const float*)d_in[2];
    const float* proj_b = (const float*)d_in[3];
    const float* ln1w   = (const float*)d_in[4];
    const float* ln1b   = (const float*)d_in[5];
    const float* ln2w   = (const float*)d_in[6];
    const float* ln2b   = (const float*)d_in[7];
    const float* w1     = (const float*)d_in[8];
    const float* b1     = (const float*)d_in[9];
    const float* w2     = (const float*)d_in[10];
    const float* b2     = (const float*)d_in[11];
    float* out = (float*)d_out;

    const int SM_QKM = (16384 + 4*2112 + 256)*4;          // 100352
    const int SM_ST  = (16384 + 2112 + 128)*4;            // 74496
    const int SM_AM  = 69632 + 67584 + 34816;             // 172032
    cudaFuncSetAttribute(k_att_qkm, cudaFuncAttributeMaxDynamicSharedMemorySize, SM_QKM);
    cudaFuncSetAttribute(k_stats1,  cudaFuncAttributeMaxDynamicSharedMemorySize, SM_ST);
    cudaFuncSetAttribute(k_am,      cudaFuncAttributeMaxDynamicSharedMemorySize, SM_AM);

    k_init<<<256, 256>>>(w1, w2);
    k_gram<<<dim3(64, 8), 256>>>(x);
    k_att_qkm<<<dim3(8, 8), 256, SM_QKM>>>(qkv_w);
    k_att_d<<<dim3(8, 8), 256>>>(proj_w);
    k_stats1<<<dim3(8, 8), 256, SM_ST>>>(proj_b);
    k_norm<<<1, 32>>>(0);
    k_am<<<dim3(256, 8), 512, SM_AM>>>(x, proj_b, ln1w, ln1b, b1, b2);
    k_norm<<<1, 32>>>(1);
    k_out<<<4096, 256>>>(ln2w, ln2b, out);
}

// round 6
// speedup vs baseline: 1.6629x; 1.0120x over previous
#include <cuda_runtime.h>
#include <cuda_bf16.h>
#include <cstdint>
#include <math.h>

#define B_ 8
#define C_ 128
#define N_ 32768
#define NEL 4194304
#define MLP_ 512
#define EPS_ 1e-5f
#define SCALE_ 0.25f
#define LDE 136
#define LDH 136
#define LDX 132
#define GLD 72
#define LDS_ 133

// ---------------- scratch (device globals; no runtime allocation) ----------
__device__ float         g_G[B_][C_][C_];
__device__ float         g_M[B_][C_][C_];
__device__ float         g_s[B_][C_];       // row sums of x (fp32)
__device__ __nv_bfloat16 g_E[B_][C_][C_];
__device__ float         g_stats[4][B_];
__device__ float         g_norm[4][B_];
__device__ __nv_bfloat16 g_W1[MLP_*C_];
__device__ __nv_bfloat16 g_W2[C_*MLP_];
__device__ float         g_y [(size_t)B_*NEL];   // z buffer

// ---------------- helpers ----------------
__device__ __forceinline__ uint32_t s2u(const void* p){
    return (uint32_t)__cvta_generic_to_shared(p);
}
__device__ __forceinline__ void ldsmx4(uint32_t* r, uint32_t a){
    asm volatile("ldmatrix.sync.aligned.m8n8.x4.shared.b16 {%0,%1,%2,%3},[%4];"
        : "=r"(r[0]),"=r"(r[1]),"=r"(r[2]),"=r"(r[3]) : "r"(a));
}
__device__ __forceinline__ void ldsmx4t(uint32_t* r, uint32_t a){
    asm volatile("ldmatrix.sync.aligned.m8n8.x4.trans.shared.b16 {%0,%1,%2,%3},[%4];"
        : "=r"(r[0]),"=r"(r[1]),"=r"(r[2]),"=r"(r[3]) : "r"(a));
}
__device__ __forceinline__ void mma_bf16(float* c, const uint32_t* a, const uint32_t* b){
    asm volatile("mma.sync.aligned.m16n8k16.row.col.f32.bf16.bf16.f32 "
        "{%0,%1,%2,%3},{%4,%5,%6,%7},{%8,%9},{%0,%1,%2,%3};"
        : "+f"(c[0]),"+f"(c[1]),"+f"(c[2]),"+f"(c[3])
        : "r"(a[0]),"r"(a[1]),"r"(a[2]),"r"(a[3]),"r"(b[0]),"r"(b[1]));
}
__device__ __forceinline__ float gelu_f(float v){
    return 0.5f*v*(1.0f+erff(v*0.70710678118654752f));
}

// ---------------- K0: zero scratch, convert MLP weights -------------------
__global__ void k_init(const float* __restrict__ w1, const float* __restrict__ w2){
    int i  = blockIdx.x*blockDim.x + threadIdx.x;
    int st = gridDim.x*blockDim.x;
    float* gg = &g_G[0][0][0];
    for(int t=i; t<B_*C_*C_; t+=st) gg[t] = 0.f;
    float* gsv = &g_s[0][0];
    for(int t=i; t<B_*C_; t+=st) gsv[t] = 0.f;
    float* gs = &g_stats[0][0];
    for(int t=i; t<4*B_; t+=st) gs[t] = 0.f;
    for(int t=i; t<MLP_*C_; t+=st) g_W1[t] = __float2bfloat16(w1[t]);
    for(int t=i; t<C_*MLP_; t+=st) g_W2[t] = __float2bfloat16(w2[t]);
}

// ---------------- K1: Gram G = X X^T  (+ row sums s) -----------------------
__global__ void __launch_bounds__(256) k_gram(const float* __restrict__ x){
    __shared__ __nv_bfloat16 Xs[C_][GLD];
    int b = blockIdx.y, split = blockIdx.x;
    const float* xb = x + (size_t)b*NEL + split*512;
    int tid = threadIdx.x, lane = tid&31, warp = tid>>5;
    float acc[16][4];
    #pragma unroll
    for(int i=0;i<16;++i){ acc[i][0]=acc[i][1]=acc[i][2]=acc[i][3]=0.f; }
    float racc[8] = {0.f,0.f,0.f,0.f,0.f,0.f,0.f,0.f};
    for(int kc=0; kc<8; ++kc){
        const float* src = xb + kc*64;
        #pragma unroll
        for(int m=0;m<8;++m){
            int idx = tid + m*256;
            int row = idx>>4, c4 = idx&15;
            float4 v = *(const float4*)(src + (size_t)row*N_ + c4*4);
            __nv_bfloat162* d = (__nv_bfloat162*)&Xs[row][c4*4];
            d[0] = __floats2bfloat162_rn(v.x, v.y);
            d[1] = __floats2bfloat162_rn(v.z, v.w);
            racc[m] += v.x+v.y+v.z+v.w;
        }
        __syncthreads();
        int m0 = warp*16;
        #pragma unroll
        for(int ks=0; ks<4; ++ks){
            int k = ks*16;
            uint32_t a[4];
            ldsmx4(a, s2u(&Xs[m0 + (lane&15)][k + ((lane>>4)&1)*8]));
            #pragma unroll
            for(int nt=0; nt<8; ++nt){
                uint32_t Bv[4];
                ldsmx4(Bv, s2u(&Xs[nt*16 + (lane&7) + ((lane>>4)&1)*8][k + ((lane>>3)&1)*8]));
                mma_bf16(acc[nt*2+0], a, Bv);
                mma_bf16(acc[nt*2+1], a, Bv+2);
            }
        }
        __syncthreads();
    }
    float* Gb = &g_G[b][0][0];
    int r0 = warp*16 + (lane>>2);
    #pragma unroll
    for(int nt=0; nt<16; ++nt){
        int c0 = nt*8 + (lane&3)*2;
        atomicAdd(&Gb[(size_t)r0*C_ + c0],       acc[nt][0]);
        atomicAdd(&Gb[(size_t)r0*C_ + c0+1],     acc[nt][1]);
        atomicAdd(&Gb[(size_t)(r0+8)*C_ + c0],   acc[nt][2]);
        atomicAdd(&Gb[(size_t)(r0+8)*C_ + c0+1], acc[nt][3]);
    }
    // row sums
    #pragma unroll
    for(int m=0;m<8;++m){
        #pragma unroll
        for(int o=8;o>0;o>>=1)
            racc[m] += __shfl_xor_sync(0xffffffffu, racc[m], o, 16);
    }
    if((tid&15)==0){
        int rb = tid>>4;
        #pragma unroll
        for(int m=0;m<8;++m)
            atomicAdd(&g_s[b][rb + 16*m], racc[m]);
    }
}

// ---------------- K2a: T = Wq*G, softmax, M = A*Wv  (rows r0..r0+31) -------
// grid (4, 8), 512 thr; all operands smem-resident
__global__ void __launch_bounds__(512) k_attA(const float* __restrict__ qkv_w){
    extern __shared__ float sa[];
    float* Gs  = sa;                   // 16384
    float* Wq  = Gs + 16384;           // 32*133
    float* Wk  = Wq + 32*LDS_;
    float* Wv  = Wk + 32*LDS_;
    float* Ts  = Wv + 32*LDS_;         // 32*133
    float* As  = Ts + 32*LDS_;         // 512
    int rg = blockIdx.x, b = blockIdx.y, tid = threadIdx.x;
    int r0 = rg*32;
    const float* Gb = &g_G[b][0][0];
    for(int i=tid; i<4096; i+=512)
        *(float4*)&Gs[i*4] = *(const float4*)&Gb[i*4];
    for(int i=tid; i<4096; i+=512){
        int r = i>>7, c = i&127;
        Wq[r*LDS_+c] = qkv_w[(size_t)(r0+r)*C_ + c];
        Wk[r*LDS_+c] = qkv_w[(size_t)(C_+r0+r)*C_ + c];
        Wv[r*LDS_+c] = qkv_w[(size_t)(2*C_+r0+r)*C_ + c];
    }
    __syncthreads();
    int il = tid>>4, tg = tid&15;
    {   // T[il][t] = sum_k Wq[il][k] * G[k][t]
        float acc[8] = {0.f,0.f,0.f,0.f,0.f,0.f,0.f,0.f};
        #pragma unroll 4
        for(int k=0;k<C_;++k){
            float w = Wq[il*LDS_+k];
            #pragma unroll
            for(int tt=0;tt<8;++tt) acc[tt] += w*Gs[k*128 + tg + tt*16];
        }
        #pragma unroll
        for(int tt=0;tt<8;++tt) Ts[il*LDS_ + tg + tt*16] = acc[tt];
    }
    __syncthreads();
    {   // logits + softmax; thread (il=row, tg=j)
        int jrow = (il>>4)*16 + tg;   // head-local Wk row
        float l = 0.f;
        #pragma unroll 4
        for(int t=0;t<C_;++t) l += Ts[il*LDS_+t]*Wk[jrow*LDS_+t];
        l *= SCALE_;
        float mx = l;
        #pragma unroll
        for(int o=8;o>0;o>>=1) mx = fmaxf(mx, __shfl_xor_sync(0xffffffffu, mx, o, 16));
        float e = expf(l-mx), s = e;
        #pragma unroll
        for(int o=8;o>0;o>>=1) s += __shfl_xor_sync(0xffffffffu, s, o, 16);
        As[il*16+tg] = e/s;
    }
    __syncthreads();
    {   // M[il][k] = sum_j A[il][j] * Wv[headlocal j][k]
        float acc[8] = {0.f,0.f,0.f,0.f,0.f,0.f,0.f,0.f};
        int jb = (il>>4)*16;
        #pragma unroll
        for(int j=0;j<16;++j){
            float a = As[il*16+j];
            #pragma unroll
            for(int kk=0;kk<8;++kk) acc[kk] += a*Wv[(jb+j)*LDS_ + tg + kk*16];
        }
        #pragma unroll
        for(int kk=0;kk<8;++kk) g_M[b][r0+il][tg+kk*16] = acc[kk];
    }
}

// ---------------- K2b: E = Wp*M (rows r0..+31) + analytic LN1 stats --------
// grid (4, 8), 512 thr
__global__ void __launch_bounds__(512) k_attB(const float* __restrict__ proj_w,
                                              const float* __restrict__ proj_b){
    extern __shared__ float sb[];
    float* Gs  = sb;                   // 16384
    float* MS  = Gs + 16384;           // 16384
    float* Wp  = MS + 16384;           // 32*133
    float* Es  = Wp + 32*LDS_;         // 32*133
    float* sv  = Es + 32*LDS_;         // 128
    float* red = sv + 128;             // 64 (32 qacc + 32 sacc)
    int rg = blockIdx.x, b = blockIdx.y, tid = threadIdx.x;
    int r0 = rg*32;
    const float* Gb = &g_G[b][0][0];
    const float* Mb = &g_M[b][0][0];
    for(int i=tid; i<4096; i+=512){
        *(float4*)&Gs[i*4] = *(const float4*)&Gb[i*4];
        *(float4*)&MS[i*4] = *(const float4*)&Mb[i*4];
    }
    for(int i=tid; i<4096; i+=512){
        int r = i>>7, c = i&127;
        Wp[r*LDS_+c] = proj_w[(size_t)(r0+r)*C_ + c];
    }
    if(tid<128) sv[tid] = g_s[b][tid];
    __syncthreads();
    int ol = tid>>4, tg = tid&15;
    {   // E[ol][k] = sum_r Wp[ol][r] * M[r][k]
        float acc[8] = {0.f,0.f,0.f,0.f,0.f,0.f,0.f,0.f};
        #pragma unroll 4
        for(int r=0;r<C_;++r){
            float w = Wp[ol*LDS_+r];
            #pragma unroll
            for(int tt=0;tt<8;++tt) acc[tt] += w*MS[r*128 + tg + tt*16];
        }
        int og = r0 + ol;
        #pragma unroll
        for(int tt=0;tt<8;++tt){
            int k = tg + tt*16;
            g_E[b][og][k] = __float2bfloat16(acc[tt]);
            // smem copy with +identity for the stats pass
            Es[ol*LDS_ + k] = acc[tt] + ((og==k) ? 1.f : 0.f);
        }
    }
    __syncthreads();
    {   // stats: row = Es[ol] (= (I+E) row r0+ol)
        // qacc = row*G*row^T ; ms = row . s
        float q = 0.f, ms = 0.f;
        #pragma unroll
        for(int tt=0;tt<8;++tt){
            int j = tg + tt*16;
            float p = 0.f;
            #pragma unroll 4
            for(int i=0;i<C_;++i) p += Es[ol*LDS_+i]*Gs[i*128 + j];
            float rj = Es[ol*LDS_+j];
            q  += p*rj;
            ms += rj*sv[j];
        }
        #pragma unroll
        for(int o=8;o>0;o>>=1){
            q  += __shfl_xor_sync(0xffffffffu, q,  o, 16);
            ms += __shfl_xor_sync(0xffffffffu, ms, o, 16);
        }
        if(tg==0){
            float pb = proj_b[r0+ol];
            red[ol]    = q + 2.f*pb*ms + (float)N_*pb*pb;
            red[32+ol] = ms + (float)N_*pb;
        }
    }
    __syncthreads();
    if(tid==0){
        float q=0.f,s=0.f;
        #pragma unroll
        for(int c=0;c<32;++c){ q+=red[c]; s+=red[32+c]; }
        atomicAdd(&g_stats[1][b], q);
        atomicAdd(&g_stats[0][b], s);
    }
}

// ---------------- K5/K7: finalize LN stats ---------------------------------
__global__ void k_norm(int stage){
    int b = threadIdx.x;
    if(b < B_){
        float s = g_stats[stage*2][b], q = g_stats[stage*2+1][b];
        float mu = s / (float)NEL;
        float var = q / (float)NEL - mu*mu;
        g_norm[stage*2][b]   = mu;
        g_norm[stage*2+1][b] = rsqrtf(var + EPS_);
    }
}

// ---------------- K6: fused apply + LN1 + MLP ------------------------------
__global__ void __launch_bounds__(512) k_am(const float* __restrict__ x,
                                            const float* __restrict__ proj_b,
                                            const float* __restrict__ ln1w,
                                            const float* __restrict__ ln1b,
                                            const float* __restrict__ b1,
                                            const float* __restrict__ b2){
    extern __shared__ char smraw[];
    __nv_bfloat16* EHs = (__nv_bfloat16*)smraw;                    // Es / Hs (69632 B)
    float*         X1f = (float*)(smraw + 69632);                  // 67584 B
    __nv_bfloat16* Xs  = (__nv_bfloat16*)(smraw + 69632 + 67584);  // 34816 B
    int b = blockIdx.y, n0 = blockIdx.x*128;
    int tid = threadIdx.x, lane = tid&31, warp = tid>>5;
    const float* xb = x + (size_t)b*NEL + n0;
    for(int idx=tid; idx<2048; idx+=512){
        int r = idx>>4, c8 = (idx&15)*8;
        *(uint4*)&EHs[r*LDE + c8] = *(const uint4*)&g_E[b][r][c8];
    }
    for(int idx=tid; idx<4096; idx+=512){
        int r = idx>>5, c4 = (idx&31)*4;
        float4 v = *(const float4*)(xb + (size_t)r*N_ + c4);
        __nv_bfloat162* d = (__nv_bfloat162*)&Xs[r*LDH + c4];
        d[0] = __floats2bfloat162_rn(v.x, v.y);
        d[1] = __floats2bfloat162_rn(v.z, v.w);
    }
    __syncthreads();
    // ---- phase A: y = E*x + x + pb; x1 = LN1(y)
    int mw = warp&7, nw = warp>>3;
    int m0 = mw*16;
    int ar = lane>>2, ac = (lane&3)*2;
    uint32_t A8[8][4];
    #pragma unroll
    for(int ks=0; ks<8; ++ks)
        ldsmx4(A8[ks], s2u(&EHs[(m0 + (lane&15))*LDE + ks*16 + ((lane>>4)&1)*8]));
    int r0 = m0 + ar;
    float pb0 = proj_b[r0], pb1 = proj_b[r0+8];
    float mu1 = g_norm[0][b], rs1 = g_norm[1][b];
    float xv[4][2][4];
    for(int ns=0; ns<4; ++ns){
        int n = nw*64 + ns*16;
        float acc[2][4] = {};
        #pragma unroll
        for(int ks=0; ks<8; ++ks){
            uint32_t Bv[4];
            ldsmx4t(Bv, s2u(&Xs[(ks*16 + (lane&7) + ((lane>>3)&1)*8)*LDH + n + ((lane>>4)&1)*8]));
            mma_bf16(acc[0], A8[ks], Bv);
            mma_bf16(acc[1], A8[ks], Bv+2);
        }
        #pragma unroll
        for(int nh=0; nh<2; ++nh){
            int cc = n + nh*8 + ac;
            float2 x0  = *(const float2*)(xb + (size_t)r0*N_ + cc);
            float2 x1v = *(const float2*)(xb + (size_t)(r0+8)*N_ + cc);
            float y00 = x0.x  + acc[nh][0] + pb0;
            float y01 = x0.y  + acc[nh][1] + pb0;
            float y10 = x1v.x + acc[nh][2] + pb1;
            float y11 = x1v.y + acc[nh][3] + pb1;
            float2 w0 = *(const float2*)(ln1w + (size_t)r0*N_ + n0 + cc);
            float2 w1 = *(const float2*)(ln1w + (size_t)(r0+8)*N_ + n0 + cc);
            float2 g0 = *(const float2*)(ln1b + (size_t)r0*N_ + n0 + cc);
            float2 g1 = *(const float2*)(ln1b + (size_t)(r0+8)*N_ + n0 + cc);
            xv[ns][nh][0] = (y00-mu1)*rs1*w0.x + g0.x;
            xv[ns][nh][1] = (y01-mu1)*rs1*w0.y + g0.y;
            xv[ns][nh][2] = (y10-mu1)*rs1*w1.x + g1.x;
            xv[ns][nh][3] = (y11-mu1)*rs1*w1.y + g1.y;
        }
    }
    __syncthreads();
    // ---- phase B: store x1 (fp32 + bf16)
    #pragma unroll
    for(int ns=0; ns<4; ++ns){
        #pragma unroll
        for(int nh=0; nh<2; ++nh){
            int cc = nw*64 + ns*16 + nh*8 + ac;
            *(float2*)&X1f[r0*LDX + cc]     = make_float2(xv[ns][nh][0], xv[ns][nh][1]);
            *(float2*)&X1f[(r0+8)*LDX + cc] = make_float2(xv[ns][nh][2], xv[ns][nh][3]);
            *(__nv_bfloat162*)&Xs[r0*LDH + cc]     = __floats2bfloat162_rn(xv[ns][nh][0], xv[ns][nh][1]);
            *(__nv_bfloat162*)&Xs[(r0+8)*LDH + cc] = __floats2bfloat162_rn(xv[ns][nh][2], xv[ns][nh][3]);
        }
    }
    __syncthreads();
    // ---- phase C: MLP
    __nv_bfloat16* Hs = EHs;
    int mw2 = warp&3, nw2 = warp>>2;
    float zacc[2][4][4];
    #pragma unroll
    for(int a=0;a<2;++a)
        #pragma unroll
        for(int c=0;c<4;++c){ zacc[a][c][0]=zacc[a][c][1]=zacc[a][c][2]=zacc[a][c][3]=0.f; }
    for(int h=0; h<2; ++h){
        int ch0 = h*256 + warp*16;
        uint32_t Wf[8][4];
        const __nv_bfloat16* w1p = g_W1 + (size_t)ch0*C_;
        #pragma unroll
        for(int ks=0;ks<8;++ks){
            const __nv_bfloat16* wp = w1p + ks*16;
            Wf[ks][0] = *(const uint32_t*)(wp + (size_t)(ar  )*C_ + ac);
            Wf[ks][1] = *(const uint32_t*)(wp + (size_t)(ar+8)*C_ + ac);
            Wf[ks][2] = *(const uint32_t*)(wp + (size_t)(ar  )*C_ + ac + 8);
            Wf[ks][3] = *(const uint32_t*)(wp + (size_t)(ar+8)*C_ + ac + 8);
        }
        float bb0 = b1[ch0 + ar], bb1 = b1[ch0 + ar + 8];
        int hr = warp*16 + ar;
        for(int ns=0; ns<8; ++ns){
            float acc[2][4] = {};
            #pragma unroll
            for(int ks=0;ks<8;++ks){
                uint32_t Bv[4];
                ldsmx4t(Bv, s2u(&Xs[(ks*16 + (lane&7) + ((lane>>3)&1)*8)*LDH + ns*16 + ((lane>>4)&1)*8]));
                mma_bf16(acc[0], Wf[ks], Bv);
                mma_bf16(acc[1], Wf[ks], Bv+2);
            }
            #pragma unroll
            for(int nh=0; nh<2; ++nh){
                int cc = ns*16 + nh*8 + ac;
                *(__nv_bfloat162*)&Hs[hr*LDH + cc] =
                    __floats2bfloat162_rn(gelu_f(acc[nh][0]+bb0), gelu_f(acc[nh][1]+bb0));
                *(__nv_bfloat162*)&Hs[(hr+8)*LDH + cc] =
                    __floats2bfloat162_rn(gelu_f(acc[nh][2]+bb1), gelu_f(acc[nh][3]+bb1));
            }
        }
        __syncthreads();
        const __nv_bfloat16* w2p = g_W2 + (size_t)(mw2*32)*MLP_ + h*256;
        #pragma unroll 4
        for(int kc=0; kc<16; ++kc){
            uint32_t Af[2][4];
            #pragma unroll
            for(int mt=0; mt<2; ++mt){
                const __nv_bfloat16* wp = w2p + (size_t)(mt*16)*MLP_ + kc*16;
                Af[mt][0] = *(const uint32_t*)(wp + (size_t)(ar  )*MLP_ + ac);
                Af[mt][1] = *(const uint32_t*)(wp + (size_t)(ar+8)*MLP_ + ac);
                Af[mt][2] = *(const uint32_t*)(wp + (size_t)(ar  )*MLP_ + ac + 8);
                Af[mt][3] = *(const uint32_t*)(wp + (size_t)(ar+8)*MLP_ + ac + 8);
            }
            #pragma unroll
            for(int nt=0; nt<2; ++nt){
                uint32_t Bv[4];
                ldsmx4t(Bv, s2u(&Hs[(kc*16 + (lane&7) + ((lane>>3)&1)*8)*LDH + nw2*32 + nt*16 + ((lane>>4)&1)*8]));
                #pragma unroll
                for(int mt=0; mt<2; ++mt){
                    mma_bf16(zacc[mt][nt*2+0], Af[mt], Bv);
                    mma_bf16(zacc[mt][nt*2+1], Af[mt], Bv+2);
                }
            }
        }
        __syncthreads();
    }
    // ---- epilogue
    float* zb = g_y + (size_t)b*NEL + n0;
    float ls = 0.f, lq = 0.f;
    #pragma unroll
    for(int mt=0; mt<2; ++mt){
        int rz = mw2*32 + mt*16 + ar;
        float bz0 = b2[rz], bz1 = b2[rz+8];
        #pragma unroll
        for(int n8=0; n8<4; ++n8){
            int cc = nw2*32 + n8*8 + ac;
            float2 xa = *(const float2*)&X1f[rz*LDX + cc];
            float2 xc = *(const float2*)&X1f[(rz+8)*LDX + cc];
            float* a = zacc[mt][n8];
            float z00 = xa.x + a[0] + bz0;
            float z01 = xa.y + a[1] + bz0;
            float z10 = xc.x + a[2] + bz1;
            float z11 = xc.y + a[3] + bz1;
            *(float2*)(zb + (size_t)rz*N_ + cc)     = make_float2(z00, z01);
            *(float2*)(zb + (size_t)(rz+8)*N_ + cc) = make_float2(z10, z11);
            ls += z00+z01+z10+z11;
            lq += z00*z00 + z01*z01 + z10*z10 + z11*z11;
        }
    }
    #pragma unroll
    for(int o=16;o>0;o>>=1){ ls += __shfl_xor_sync(0xffffffffu, ls, o);
                             lq += __shfl_xor_sync(0xffffffffu, lq, o); }
    if(lane==0){ atomicAdd(&g_stats[2][b], ls); atomicAdd(&g_stats[3][b], lq); }
}

// ---------------- K8: out = LN2(z) -----------------------------------------
__global__ void __launch_bounds__(256) k_out(const float* __restrict__ w,
                                             const float* __restrict__ bb,
                                             float* __restrict__ out){
    size_t nv = (size_t)NEL/4;
    size_t st = (size_t)gridDim.x*blockDim.x;
    for(size_t v = (size_t)blockIdx.x*blockDim.x + threadIdx.x; v < nv; v += st){
        size_t t = v*4;
        float4 wv = *(const float4*)(w + t);
        float4 bv = *(const float4*)(bb + t);
        #pragma unroll
        for(int b=0;b<B_;++b){
            float mu = g_norm[2][b], rs = g_norm[3][b];
            float4 z  = *(const float4*)(g_y + (size_t)b*NEL + t);
            float4 o;
            o.x = (z.x-mu)*rs*wv.x + bv.x;
            o.y = (z.y-mu)*rs*wv.y + bv.y;
            o.z = (z.z-mu)*rs*wv.z + bv.z;
            o.w = (z.w-mu)*rs*wv.w + bv.w;
            *(float4*)(out + (size_t)b*NEL + t) = o;
        }
    }
}

// ---------------- launch ----------------------------------------------------
extern "C" void kernel_launch(void* const* d_in, const int* in_sizes, int n_in,
                              void* d_out, int out_size){
    const float* x      = (const float*)d_in[0];
    const float* qkv_w  = (const float*)d_in[1];
    const float* proj_w = (const float*)d_in[2];
    const float* proj_b = (const float*)d_in[3];
    const float* ln1w   = (const float*)d_in[4];
    const float* ln1b   = (const float*)d_in[5];
    const float* ln2w   = (const float*)d_in[6];
    const float* ln2b   = (const float*)d_in[7];
    const float* w1     = (const float*)d_in[8];
    const float* b1     = (const float*)d_in[9];
    const float* w2     = (const float*)d_in[10];
    const float* b2     = (const float*)d_in[11];
    float* out = (float*)d_out;

    const int SM_A  = (16384 + 4*32*LDS_ + 512)*4;                 // 152704
    const int SM_B  = (16384*2 + 2*32*LDS_ + 128 + 64)*4;          // 166144
    const int SM_AM = 69632 + 67584 + 34816;                       // 172032
    cudaFuncSetAttribute(k_attA, cudaFuncAttributeMaxDynamicSharedMemorySize, SM_A);
    cudaFuncSetAttribute(k_attB, cudaFuncAttributeMaxDynamicSharedMemorySize, SM_B);
    cudaFuncSetAttribute(k_am,   cudaFuncAttributeMaxDynamicSharedMemorySize, SM_AM);

    k_init<<<256, 256>>>(w1, w2);
    k_gram<<<dim3(64, 8), 256>>>(x);
    k_attA<<<dim3(4, 8), 512, SM_A>>>(qkv_w);
    k_attB<<<dim3(4, 8), 512, SM_B>>>(proj_w, proj_b);
    k_norm<<<1, 32>>>(0);
    k_am<<<dim3(256, 8), 512, SM_AM>>>(x, proj_b, ln1w, ln1b, b1, b2);
    k_norm<<<1, 32>>>(1);
    k_out<<<4096, 256>>>(ln2w, ln2b, out);
}

// round 7
// speedup vs baseline: 1.7981x; 1.0813x over previous
#include <cuda_runtime.h>
#include <cuda_bf16.h>
#include <cstdint>
#include <math.h>

#define B_ 8
#define C_ 128
#define N_ 32768
#define NEL 4194304
#define MLP_ 512
#define EPS_ 1e-5f
#define SCALE_ 0.25f
#define LDE 136
#define LDH2 72
#define LDX2 68
#define GLD 72
#define LDS_ 133

// ---------------- scratch ----------------
__device__ float         g_G[B_][C_][C_];
__device__ float         g_M[B_][C_][C_];
__device__ float         g_s[B_][C_];
__device__ __nv_bfloat16 g_E[B_][C_][C_];
__device__ float         g_stats[4][B_];
__device__ float         g_norm[4][B_];
__device__ __nv_bfloat16 g_W1[MLP_*C_];
__device__ __nv_bfloat16 g_W2[C_*MLP_];
__device__ float         g_y [(size_t)B_*NEL];

// ---------------- helpers ----------------
__device__ __forceinline__ uint32_t s2u(const void* p){
    return (uint32_t)__cvta_generic_to_shared(p);
}
__device__ __forceinline__ void ldsmx4(uint32_t* r, uint32_t a){
    asm volatile("ldmatrix.sync.aligned.m8n8.x4.shared.b16 {%0,%1,%2,%3},[%4];"
        : "=r"(r[0]),"=r"(r[1]),"=r"(r[2]),"=r"(r[3]) : "r"(a));
}
__device__ __forceinline__ void ldsmx4t(uint32_t* r, uint32_t a){
    asm volatile("ldmatrix.sync.aligned.m8n8.x4.trans.shared.b16 {%0,%1,%2,%3},[%4];"
        : "=r"(r[0]),"=r"(r[1]),"=r"(r[2]),"=r"(r[3]) : "r"(a));
}
__device__ __forceinline__ void mma_bf16(float* c, const uint32_t* a, const uint32_t* b){
    asm volatile("mma.sync.aligned.m16n8k16.row.col.f32.bf16.bf16.f32 "
        "{%0,%1,%2,%3},{%4,%5,%6,%7},{%8,%9},{%0,%1,%2,%3};"
        : "+f"(c[0]),"+f"(c[1]),"+f"(c[2]),"+f"(c[3])
        : "r"(a[0]),"r"(a[1]),"r"(a[2]),"r"(a[3]),"r"(b[0]),"r"(b[1]));
}
__device__ __forceinline__ float gelu_f(float v){
    return 0.5f*v*(1.0f+erff(v*0.70710678118654752f));
}

// ---------------- K0 ----------------
__global__ void k_init(const float* __restrict__ w1, const float* __restrict__ w2){
    int i  = blockIdx.x*blockDim.x + threadIdx.x;
    int st = gridDim.x*blockDim.x;
    float* gg = &g_G[0][0][0];
    for(int t=i; t<B_*C_*C_; t+=st) gg[t] = 0.f;
    float* gsv = &g_s[0][0];
    for(int t=i; t<B_*C_; t+=st) gsv[t] = 0.f;
    float* gs = &g_stats[0][0];
    for(int t=i; t<4*B_; t+=st) gs[t] = 0.f;
    for(int t=i; t<MLP_*C_; t+=st) g_W1[t] = __float2bfloat16(w1[t]);
    for(int t=i; t<C_*MLP_; t+=st) g_W2[t] = __float2bfloat16(w2[t]);
}

// ---------------- K1: Gram G = X X^T (+ row sums) --------------------------
__global__ void __launch_bounds__(256) k_gram(const float* __restrict__ x){
    __shared__ __nv_bfloat16 Xs[C_][GLD];
    int b = blockIdx.y, split = blockIdx.x;
    const float* xb = x + (size_t)b*NEL + split*512;
    int tid = threadIdx.x, lane = tid&31, warp = tid>>5;
    float acc[16][4];
    #pragma unroll
    for(int i=0;i<16;++i){ acc[i][0]=acc[i][1]=acc[i][2]=acc[i][3]=0.f; }
    float racc[8] = {0.f,0.f,0.f,0.f,0.f,0.f,0.f,0.f};
    for(int kc=0; kc<8; ++kc){
        const float* src = xb + kc*64;
        #pragma unroll
        for(int m=0;m<8;++m){
            int idx = tid + m*256;
            int row = idx>>4, c4 = idx&15;
            float4 v = *(const float4*)(src + (size_t)row*N_ + c4*4);
            __nv_bfloat162* d = (__nv_bfloat162*)&Xs[row][c4*4];
            d[0] = __floats2bfloat162_rn(v.x, v.y);
            d[1] = __floats2bfloat162_rn(v.z, v.w);
            racc[m] += v.x+v.y+v.z+v.w;
        }
        __syncthreads();
        int m0 = warp*16;
        #pragma unroll
        for(int ks=0; ks<4; ++ks){
            int k = ks*16;
            uint32_t a[4];
            ldsmx4(a, s2u(&Xs[m0 + (lane&15)][k + ((lane>>4)&1)*8]));
            #pragma unroll
            for(int nt=0; nt<8; ++nt){
                uint32_t Bv[4];
                ldsmx4(Bv, s2u(&Xs[nt*16 + (lane&7) + ((lane>>4)&1)*8][k + ((lane>>3)&1)*8]));
                mma_bf16(acc[nt*2+0], a, Bv);
                mma_bf16(acc[nt*2+1], a, Bv+2);
            }
        }
        __syncthreads();
    }
    float* Gb = &g_G[b][0][0];
    int r0 = warp*16 + (lane>>2);
    #pragma unroll
    for(int nt=0; nt<16; ++nt){
        int c0 = nt*8 + (lane&3)*2;
        atomicAdd(&Gb[(size_t)r0*C_ + c0],       acc[nt][0]);
        atomicAdd(&Gb[(size_t)r0*C_ + c0+1],     acc[nt][1]);
        atomicAdd(&Gb[(size_t)(r0+8)*C_ + c0],   acc[nt][2]);
        atomicAdd(&Gb[(size_t)(r0+8)*C_ + c0+1], acc[nt][3]);
    }
    #pragma unroll
    for(int m=0;m<8;++m){
        #pragma unroll
        for(int o=8;o>0;o>>=1)
            racc[m] += __shfl_xor_sync(0xffffffffu, racc[m], o, 16);
    }
    if((tid&15)==0){
        int rb = tid>>4;
        #pragma unroll
        for(int m=0;m<8;++m)
            atomicAdd(&g_s[b][rb + 16*m], racc[m]);
    }
}

// ---------------- K2a: T = Wq*G, softmax, M = A*Wv -------------------------
__global__ void __launch_bounds__(1024) k_attA(const float* __restrict__ qkv_w){
    extern __shared__ float sa[];
    float* Gs  = sa;                   // 16384
    float* Wq  = Gs + 16384;
    float* Wk  = Wq + 32*LDS_;
    float* Wv  = Wk + 32*LDS_;
    float* Ts  = Wv + 32*LDS_;
    float* As  = Ts + 32*LDS_;         // 512
    int rg = blockIdx.x, b = blockIdx.y, tid = threadIdx.x;
    int r0 = rg*32;
    const float* Gb = &g_G[b][0][0];
    for(int i=tid; i<4096; i+=1024)
        *(float4*)&Gs[i*4] = *(const float4*)&Gb[i*4];
    for(int i=tid; i<4096; i+=1024){
        int r = i>>7, c = i&127;
        Wq[r*LDS_+c] = qkv_w[(size_t)(r0+r)*C_ + c];
        Wk[r*LDS_+c] = qkv_w[(size_t)(C_+r0+r)*C_ + c];
        Wv[r*LDS_+c] = qkv_w[(size_t)(2*C_+r0+r)*C_ + c];
    }
    __syncthreads();
    int il = tid>>5, tg = tid&31;
    {   // T[il][t]
        float acc[4] = {0.f,0.f,0.f,0.f};
        #pragma unroll 4
        for(int k=0;k<C_;++k){
            float w = Wq[il*LDS_+k];
            #pragma unroll
            for(int tt=0;tt<4;++tt) acc[tt] += w*Gs[k*128 + tg + tt*32];
        }
        #pragma unroll
        for(int tt=0;tt<4;++tt) Ts[il*LDS_ + tg + tt*32] = acc[tt];
    }
    __syncthreads();
    if(tid < 512){   // logits + softmax
        int ir = tid>>4, jg = tid&15;
        int jrow = (ir>>4)*16 + jg;
        float l = 0.f;
        #pragma unroll 4
        for(int t=0;t<C_;++t) l += Ts[ir*LDS_+t]*Wk[jrow*LDS_+t];
        l *= SCALE_;
        float mx = l;
        #pragma unroll
        for(int o=8;o>0;o>>=1) mx = fmaxf(mx, __shfl_xor_sync(0xffffffffu, mx, o, 16));
        float e = expf(l-mx), s = e;
        #pragma unroll
        for(int o=8;o>0;o>>=1) s += __shfl_xor_sync(0xffffffffu, s, o, 16);
        As[ir*16+jg] = e/s;
    }
    __syncthreads();
    {   // M[il][k]
        float acc[4] = {0.f,0.f,0.f,0.f};
        int jb = (il>>4)*16;
        #pragma unroll
        for(int j=0;j<16;++j){
            float a = As[il*16+j];
            #pragma unroll
            for(int kk=0;kk<4;++kk) acc[kk] += a*Wv[(jb+j)*LDS_ + tg + kk*32];
        }
        #pragma unroll
        for(int kk=0;kk<4;++kk) g_M[b][r0+il][tg+kk*32] = acc[kk];
    }
}

// ---------------- K2b: E = Wp*M + analytic LN1 stats -----------------------
__global__ void __launch_bounds__(1024) k_attB(const float* __restrict__ proj_w,
                                               const float* __restrict__ proj_b){
    extern __shared__ float sb[];
    float* Gs  = sb;                   // 16384
    float* MS  = Gs + 16384;           // 16384
    float* Wp  = MS + 16384;           // 32*133
    float* Es  = Wp + 32*LDS_;         // 32*133
    float* sv  = Es + 32*LDS_;         // 128
    float* red = sv + 128;             // 64
    int rg = blockIdx.x, b = blockIdx.y, tid = threadIdx.x;
    int r0 = rg*32;
    const float* Gb = &g_G[b][0][0];
    const float* Mb = &g_M[b][0][0];
    for(int i=tid; i<4096; i+=1024){
        *(float4*)&Gs[i*4] = *(const float4*)&Gb[i*4];
        *(float4*)&MS[i*4] = *(const float4*)&Mb[i*4];
    }
    for(int i=tid; i<4096; i+=1024){
        int r = i>>7, c = i&127;
        Wp[r*LDS_+c] = proj_w[(size_t)(r0+r)*C_ + c];
    }
    if(tid<128) sv[tid] = g_s[b][tid];
    __syncthreads();
    int ol = tid>>5, tg = tid&31;
    {   // E row
        float acc[4] = {0.f,0.f,0.f,0.f};
        #pragma unroll 4
        for(int r=0;r<C_;++r){
            float w = Wp[ol*LDS_+r];
            #pragma unroll
            for(int tt=0;tt<4;++tt) acc[tt] += w*MS[r*128 + tg + tt*32];
        }
        int og = r0 + ol;
        #pragma unroll
        for(int tt=0;tt<4;++tt){
            int k = tg + tt*32;
            g_E[b][og][k] = __float2bfloat16(acc[tt]);
            Es[ol*LDS_ + k] = acc[tt] + ((og==k) ? 1.f : 0.f);
        }
    }
    __syncthreads();
    {   // stats
        float q = 0.f, ms = 0.f;
        #pragma unroll
        for(int tt=0;tt<4;++tt){
            int j = tg + tt*32;
            float p = 0.f;
            #pragma unroll 4
            for(int i=0;i<C_;++i) p += Es[ol*LDS_+i]*Gs[i*128 + j];
            float rj = Es[ol*LDS_+j];
            q  += p*rj;
            ms += rj*sv[j];
        }
        #pragma unroll
        for(int o=16;o>0;o>>=1){
            q  += __shfl_xor_sync(0xffffffffu, q,  o);
            ms += __shfl_xor_sync(0xffffffffu, ms, o);
        }
        if(tg==0){
            float pb = proj_b[r0+ol];
            red[ol]    = q + 2.f*pb*ms + (float)N_*pb*pb;
            red[32+ol] = ms + (float)N_*pb;
        }
    }
    __syncthreads();
    if(tid==0){
        float q=0.f,s=0.f;
        #pragma unroll
        for(int c=0;c<32;++c){ q+=red[c]; s+=red[32+c]; }
        atomicAdd(&g_stats[1][b], q);
        atomicAdd(&g_stats[0][b], s);
    }
}

// ---------------- K5/K7: finalize LN stats ---------------------------------
__global__ void k_norm(int stage){
    int b = threadIdx.x;
    if(b < B_){
        float s = g_stats[stage*2][b], q = g_stats[stage*2+1][b];
        float mu = s / (float)NEL;
        float var = q / (float)NEL - mu*mu;
        g_norm[stage*2][b]   = mu;
        g_norm[stage*2+1][b] = rsqrtf(var + EPS_);
    }
}

// ---------------- K6: fused apply + LN1 + MLP (64-wide tiles, 1024 thr) ----
__global__ void __launch_bounds__(1024) k_am(const float* __restrict__ x,
                                             const float* __restrict__ proj_b,
                                             const float* __restrict__ ln1w,
                                             const float* __restrict__ ln1b,
                                             const float* __restrict__ b1,
                                             const float* __restrict__ b2){
    extern __shared__ char smraw[];
    __nv_bfloat16* Hs  = (__nv_bfloat16*)smraw;                  // 512*72*2 = 73728 (Es first)
    float*         X1f = (float*)(smraw + 73728);                // 128*68*4 = 34816
    __nv_bfloat16* Xs  = (__nv_bfloat16*)(smraw + 73728+34816);  // 128*72*2 = 18432 (W2s later)
    __nv_bfloat16* Es  = Hs;
    __nv_bfloat16* W2s = Xs;
    int b = blockIdx.y, n0 = blockIdx.x*64;
    int tid = threadIdx.x, lane = tid&31, warp = tid>>5;
    const float* xb = x + (size_t)b*NEL + n0;
    // load E (128x128 bf16) into Es and x tile (128x64) into Xs
    #pragma unroll
    for(int m=0;m<2;++m){
        int idx = tid + m*1024;
        int r = idx>>4, c8 = (idx&15)*8;
        *(uint4*)&Es[r*LDE + c8] = *(const uint4*)&g_E[b][r][c8];
    }
    #pragma unroll
    for(int m=0;m<2;++m){
        int idx = tid + m*1024;
        int r = idx>>4, c4 = (idx&15)*4;
        float4 v = *(const float4*)(xb + (size_t)r*N_ + c4);
        __nv_bfloat162* d = (__nv_bfloat162*)&Xs[r*LDH2 + c4];
        d[0] = __floats2bfloat162_rn(v.x, v.y);
        d[1] = __floats2bfloat162_rn(v.z, v.w);
    }
    __syncthreads();
    // ---- phase A: y = E*x + x + pb; x1 = LN1(y) (regs)
    int mw = warp&7, nw = warp>>3;   // 8 x 4
    int m0 = mw*16, n = nw*16;
    int ar = lane>>2, ac = (lane&3)*2;
    int r0 = m0 + ar;
    float xv[2][4];
    {
        uint32_t A8[8][4];
        #pragma unroll
        for(int ks=0; ks<8; ++ks)
            ldsmx4(A8[ks], s2u(&Es[(m0 + (lane&15))*LDE + ks*16 + ((lane>>4)&1)*8]));
        float acc[2][4] = {};
        #pragma unroll
        for(int ks=0; ks<8; ++ks){
            uint32_t Bv[4];
            ldsmx4t(Bv, s2u(&Xs[(ks*16 + (lane&7) + ((lane>>3)&1)*8)*LDH2 + n + ((lane>>4)&1)*8]));
            mma_bf16(acc[0], A8[ks], Bv);
            mma_bf16(acc[1], A8[ks], Bv+2);
        }
        float pb0 = proj_b[r0], pb1 = proj_b[r0+8];
        float mu1 = g_norm[0][b], rs1 = g_norm[1][b];
        #pragma unroll
        for(int nh=0; nh<2; ++nh){
            int cc = n + nh*8 + ac;
            float2 x0  = *(const float2*)(xb + (size_t)r0*N_ + cc);
            float2 x1v = *(const float2*)(xb + (size_t)(r0+8)*N_ + cc);
            float y00 = x0.x  + acc[nh][0] + pb0;
            float y01 = x0.y  + acc[nh][1] + pb0;
            float y10 = x1v.x + acc[nh][2] + pb1;
            float y11 = x1v.y + acc[nh][3] + pb1;
            float2 w0 = *(const float2*)(ln1w + (size_t)r0*N_ + n0 + cc);
            float2 w1 = *(const float2*)(ln1w + (size_t)(r0+8)*N_ + n0 + cc);
            float2 g0 = *(const float2*)(ln1b + (size_t)r0*N_ + n0 + cc);
            float2 g1 = *(const float2*)(ln1b + (size_t)(r0+8)*N_ + n0 + cc);
            xv[nh][0] = (y00-mu1)*rs1*w0.x + g0.x;
            xv[nh][1] = (y01-mu1)*rs1*w0.y + g0.y;
            xv[nh][2] = (y10-mu1)*rs1*w1.x + g1.x;
            xv[nh][3] = (y11-mu1)*rs1*w1.y + g1.y;
        }
    }
    __syncthreads();
    // ---- phase B: store x1 (fp32 + bf16)
    #pragma unroll
    for(int nh=0; nh<2; ++nh){
        int cc = n + nh*8 + ac;
        *(float2*)&X1f[r0*LDX2 + cc]     = make_float2(xv[nh][0], xv[nh][1]);
        *(float2*)&X1f[(r0+8)*LDX2 + cc] = make_float2(xv[nh][2], xv[nh][3]);
        *(__nv_bfloat162*)&Xs[r0*LDH2 + cc]     = __floats2bfloat162_rn(xv[nh][0], xv[nh][1]);
        *(__nv_bfloat162*)&Xs[(r0+8)*LDH2 + cc] = __floats2bfloat162_rn(xv[nh][2], xv[nh][3]);
    }
    __syncthreads();
    // ---- GEMM1: hid = gelu(W1 x1 + b1): 32 warps x 16 rows = 512 rows
    {
        int ch0 = warp*16;
        uint32_t Wf[8][4];
        const __nv_bfloat16* w1p = g_W1 + (size_t)ch0*C_;
        #pragma unroll
        for(int ks=0;ks<8;++ks){
            const __nv_bfloat16* wp = w1p + ks*16;
            Wf[ks][0] = *(const uint32_t*)(wp + (size_t)(ar  )*C_ + ac);
            Wf[ks][1] = *(const uint32_t*)(wp + (size_t)(ar+8)*C_ + ac);
            Wf[ks][2] = *(const uint32_t*)(wp + (size_t)(ar  )*C_ + ac + 8);
            Wf[ks][3] = *(const uint32_t*)(wp + (size_t)(ar+8)*C_ + ac + 8);
        }
        float bb0 = b1[ch0 + ar], bb1 = b1[ch0 + ar + 8];
        int hr = ch0 + ar;
        #pragma unroll
        for(int ns=0; ns<4; ++ns){
            float acc[2][4] = {};
            #pragma unroll
            for(int ks=0;ks<8;++ks){
                uint32_t Bv[4];
                ldsmx4t(Bv, s2u(&Xs[(ks*16 + (lane&7) + ((lane>>3)&1)*8)*LDH2 + ns*16 + ((lane>>4)&1)*8]));
                mma_bf16(acc[0], Wf[ks], Bv);
                mma_bf16(acc[1], Wf[ks], Bv+2);
            }
            #pragma unroll
            for(int nh=0; nh<2; ++nh){
                int cc = ns*16 + nh*8 + ac;
                *(__nv_bfloat162*)&Hs[hr*LDH2 + cc] =
                    __floats2bfloat162_rn(gelu_f(acc[nh][0]+bb0), gelu_f(acc[nh][1]+bb0));
                *(__nv_bfloat162*)&Hs[(hr+8)*LDH2 + cc] =
                    __floats2bfloat162_rn(gelu_f(acc[nh][2]+bb1), gelu_f(acc[nh][3]+bb1));
            }
        }
    }
    // ---- GEMM2: z = W2 * hid (k=512, staged in 64-k chunks through smem)
    float zacc[2][4] = {};
    int m0b = (warp&7)*16, nb = (warp>>3)*16;
    for(int c0=0; c0<MLP_; c0+=64){
        __syncthreads();   // prev chunk readers done (also covers GEMM1 -> staging)
        {
            int r = tid>>3, u = tid&7;
            *(uint4*)&W2s[r*LDH2 + u*8] = *(const uint4*)&g_W2[(size_t)r*MLP_ + c0 + u*8];
        }
        __syncthreads();
        #pragma unroll
        for(int ks2=0; ks2<4; ++ks2){
            uint32_t Af[4], Bv[4];
            ldsmx4(Af, s2u(&W2s[(m0b + (lane&15))*LDH2 + ks2*16 + ((lane>>4)&1)*8]));
            ldsmx4t(Bv, s2u(&Hs[(c0 + ks2*16 + (lane&7) + ((lane>>3)&1)*8)*LDH2 + nb + ((lane>>4)&1)*8]));
            mma_bf16(zacc[0], Af, Bv);
            mma_bf16(zacc[1], Af, Bv+2);
        }
    }
    // ---- epilogue: z = x1 + zacc + b2; LN2 stats
    float* zb = g_y + (size_t)b*NEL + n0;
    int rz = m0b + ar;
    float bz0 = b2[rz], bz1 = b2[rz+8];
    float ls = 0.f, lq = 0.f;
    #pragma unroll
    for(int nh=0; nh<2; ++nh){
        int cc = nb + nh*8 + ac;
        float2 xa = *(const float2*)&X1f[rz*LDX2 + cc];
        float2 xc = *(const float2*)&X1f[(rz+8)*LDX2 + cc];
        float z00 = xa.x + zacc[nh][0] + bz0;
        float z01 = xa.y + zacc[nh][1] + bz0;
        float z10 = xc.x + zacc[nh][2] + bz1;
        float z11 = xc.y + zacc[nh][3] + bz1;
        *(float2*)(zb + (size_t)rz*N_ + cc)     = make_float2(z00, z01);
        *(float2*)(zb + (size_t)(rz+8)*N_ + cc) = make_float2(z10, z11);
        ls += z00+z01+z10+z11;
        lq += z00*z00 + z01*z01 + z10*z10 + z11*z11;
    }
    #pragma unroll
    for(int o=16;o>0;o>>=1){ ls += __shfl_xor_sync(0xffffffffu, ls, o);
                             lq += __shfl_xor_sync(0xffffffffu, lq, o); }
    if(lane==0){ atomicAdd(&g_stats[2][b], ls); atomicAdd(&g_stats[3][b], lq); }
}

// ---------------- K8: out = LN2(z) -----------------------------------------
__global__ void __launch_bounds__(256) k_out(const float* __restrict__ w,
                                             const float* __restrict__ bb,
                                             float* __restrict__ out){
    size_t nv = (size_t)NEL/4;
    size_t st = (size_t)gridDim.x*blockDim.x;
    for(size_t v = (size_t)blockIdx.x*blockDim.x + threadIdx.x; v < nv; v += st){
        size_t t = v*4;
        float4 wv = *(const float4*)(w + t);
        float4 bv = *(const float4*)(bb + t);
        #pragma unroll
        for(int b=0;b<B_;++b){
            float mu = g_norm[2][b], rs = g_norm[3][b];
            float4 z  = *(const float4*)(g_y + (size_t)b*NEL + t);
            float4 o;
            o.x = (z.x-mu)*rs*wv.x + bv.x;
            o.y = (z.y-mu)*rs*wv.y + bv.y;
            o.z = (z.z-mu)*rs*wv.z + bv.z;
            o.w = (z.w-mu)*rs*wv.w + bv.w;
            *(float4*)(out + (size_t)b*NEL + t) = o;
        }
    }
}

// ---------------- launch ----------------------------------------------------
extern "C" void kernel_launch(void* const* d_in, const int* in_sizes, int n_in,
                              void* d_out, int out_size){
    const float* x      = (const float*)d_in[0];
    const float* qkv_w  = (const float*)d_in[1];
    const float* proj_w = (const float*)d_in[2];
    const float* proj_b = (const float*)d_in[3];
    const float* ln1w   = (const float*)d_in[4];
    const float* ln1b   = (const float*)d_in[5];
    const float* ln2w   = (const float*)d_in[6];
    const float* ln2b   = (const float*)d_in[7];
    const float* w1     = (const float*)d_in[8];
    const float* b1     = (const float*)d_in[9];
    const float* w2     = (const float*)d_in[10];
    const float* b2     = (const float*)d_in[11];
    float* out = (float*)d_out;

    const int SM_A  = (16384 + 4*32*LDS_ + 512)*4;                 // 152704
    const int SM_B  = (16384*2 + 2*32*LDS_ + 128 + 64)*4;          // 166144
    const int SM_AM = 73728 + 34816 + 18432;                       // 126976
    cudaFuncSetAttribute(k_attA, cudaFuncAttributeMaxDynamicSharedMemorySize, SM_A);
    cudaFuncSetAttribute(k_attB, cudaFuncAttributeMaxDynamicSharedMemorySize, SM_B);
    cudaFuncSetAttribute(k_am,   cudaFuncAttributeMaxDynamicSharedMemorySize, SM_AM);

    k_init<<<256, 256>>>(w1, w2);
    k_gram<<<dim3(64, 8), 256>>>(x);
    k_attA<<<dim3(4, 8), 1024, SM_A>>>(qkv_w);
    k_attB<<<dim3(4, 8), 1024, SM_B>>>(proj_w, proj_b);
    k_norm<<<1, 32>>>(0);
    k_am<<<dim3(512, 8), 1024, SM_AM>>>(x, proj_b, ln1w, ln1b, b1, b2);
    k_norm<<<1, 32>>>(1);
    k_out<<<4096, 256>>>(ln2w, ln2b, out);
}